// round 11
// baseline (speedup 1.0000x reference)
#include <cuda_runtime.h>
#include <cuda_fp16.h>
#include <math.h>
#include <cstdint>

// ---------------------------------------------------------------------------
// Problem constants
// ---------------------------------------------------------------------------
#define B_   2
#define S_   2048
#define CTX_ 256
#define D_   1024
#define H_   16
#define DH_  64
#define INNER_ 1024
#define DFF_ 4096
#define EMB_N   (3*B_*2*D_)    // 12288
#define EMB_KS  8

__device__ __forceinline__ uint32_t smem_u32(const void* p) {
    uint32_t a;
    asm("{ .reg .u64 t; cvta.to.shared.u64 t, %1; cvt.u32.u64 %0, t; }"
        : "=r"(a) : "l"(p));
    return a;
}
__device__ __forceinline__ void cp16(uint32_t dst, const void* src) {
    asm volatile("cp.async.cg.shared.global [%0], [%1], 16;" :: "r"(dst), "l"(src));
}
#define CP_COMMIT()  asm volatile("cp.async.commit_group;" ::: "memory")
#define CP_WAIT0()   asm volatile("cp.async.wait_group 0;" ::: "memory")
#define CP_WAIT1()   asm volatile("cp.async.wait_group 1;" ::: "memory")

__device__ __forceinline__ float ex2f(float x) {
    float y;
    asm("ex2.approx.f32 %0, %1;" : "=f"(y) : "f"(x));
    return y;
}
__device__ __forceinline__ uint32_t h2_u32(__half2 h) {
    union { __half2 h; uint32_t u; } c;
    c.h = h;
    return c.u;
}
__device__ __forceinline__ void mma_f16(float* c, const uint32_t* a, const uint32_t* b) {
    asm volatile(
        "mma.sync.aligned.m16n8k16.row.col.f32.f16.f16.f32 "
        "{%0,%1,%2,%3}, {%4,%5,%6,%7}, {%8,%9}, {%0,%1,%2,%3};"
        : "+f"(c[0]), "+f"(c[1]), "+f"(c[2]), "+f"(c[3])
        : "r"(a[0]), "r"(a[1]), "r"(a[2]), "r"(a[3]), "r"(b[0]), "r"(b[1]));
}
__device__ __forceinline__ void ldmx4(uint32_t* r, uint32_t addr) {
    asm volatile("ldmatrix.sync.aligned.m8n8.x4.shared.b16 {%0,%1,%2,%3}, [%4];"
        : "=r"(r[0]), "=r"(r[1]), "=r"(r[2]), "=r"(r[3]) : "r"(addr));
}
__device__ __forceinline__ void ldmx2t(uint32_t& b0, uint32_t& b1, uint32_t addr) {
    asm volatile("ldmatrix.sync.aligned.m8n8.x2.trans.shared.b16 {%0,%1}, [%2];"
        : "=r"(b0), "=r"(b1) : "r"(addr));
}

// ---------------------------------------------------------------------------
// Scratch (static device globals)
// ---------------------------------------------------------------------------
__device__ float  g_x   [B_*S_*D_];
__device__ float  g_emb [EMB_N];
__device__ float  g_embp[EMB_KS*EMB_N];
__device__ float  g_b1i [2*DFF_];
__device__ __half g_hh  [B_*S_*D_];
__device__ __half g_qh  [B_*S_*INNER_];
__device__ __half g_qkvh[B_*S_*3*INNER_];
__device__ __half g_kvh [B_*CTX_*2*INNER_];
__device__ __half g_atth[B_*S_*INNER_];
__device__ __half g_gluh[B_*S_*DFF_];
__device__ __half g_ctxh[B_*CTX_*D_];
__device__ __half g_qkv1T[3*INNER_*D_];
__device__ __half g_a1woT[D_*INNER_];
__device__ __half g_a2wqT[INNER_*D_];
__device__ __half g_kv2T [2*INNER_*D_];
__device__ __half g_a2woT[D_*INNER_];
__device__ __half g_ffw1T[2*DFF_*D_];     // GLU-interleaved rows
__device__ __half g_ffw2T[D_*DFF_];

// ---------------------------------------------------------------------------
// Merged weight prep
// ---------------------------------------------------------------------------
struct PrepSeg {
    const float* src;
    __half* dst;
    int R, C;
    int glu;
    int tile0;
};
struct PrepParams {
    PrepSeg seg[10];
    int total;
};

__global__ void __launch_bounds__(256) prep_kernel(PrepParams P) {
    __shared__ float t[32][33];
    int bid = blockIdx.x;
    int si = 0;
    #pragma unroll
    for (int i = 1; i < 10; i++)
        if (bid >= P.seg[i].tile0) si = i;
    const PrepSeg sg = P.seg[si];
    int local = bid - sg.tile0;
    int tilesX = sg.C >> 5;
    int bx = (local % tilesX) << 5;
    int by = (local / tilesX) << 5;

    int tx = threadIdx.x & 31, ty = threadIdx.x >> 5;
    int x = bx + tx;
    #pragma unroll
    for (int i = 0; i < 4; i++) {
        int y = by + ty + i * 8;
        t[ty + i*8][tx] = sg.src[(size_t)y * sg.C + x];
    }
    __syncthreads();
    int x2 = by + tx;
    #pragma unroll
    for (int i = 0; i < 4; i++) {
        int c = bx + ty + i * 8;
        int nr = c;
        if (sg.glu) nr = (c < DFF_) ? 2*c : 2*(c - DFF_) + 1;
        sg.dst[(size_t)nr * sg.R + x2] = __float2half_rn(t[tx][ty + i*8]);
    }
}

__global__ void cvt_h_kernel(const float* __restrict__ src, __half* __restrict__ dst) {
    int i = blockIdx.x * blockDim.x + threadIdx.x;
    dst[i] = __float2half_rn(src[i]);
}
__global__ void bias_ilv_kernel(const float* __restrict__ b, float* __restrict__ bi) {
    int j = blockIdx.x * blockDim.x + threadIdx.x;
    bi[2*j]   = b[j];
    bi[2*j+1] = b[DFF_ + j];
}

// ---------------------------------------------------------------------------
// Split-K AdaLN embedding
// ---------------------------------------------------------------------------
__global__ void emb_sk_kernel(const float* __restrict__ t,
                              const float* __restrict__ W0,
                              const float* __restrict__ W1,
                              const float* __restrict__ W2,
                              float* __restrict__ embp) {
    int j  = blockIdx.x * blockDim.x + threadIdx.x;
    int ks = blockIdx.y;
    int p  = j / (B_*2*D_);
    int r  = j - p * (B_*2*D_);
    int b  = r / (2*D_);
    int jj = r - b * (2*D_);
    const float* W = (p == 0) ? W0 : (p == 1) ? W1 : W2;
    const float* tr = t + b * D_ + ks * (D_/EMB_KS);
    const float* Wp = W + (size_t)(ks * (D_/EMB_KS)) * (2*D_) + jj;
    float acc = 0.f;
    #pragma unroll 8
    for (int k = 0; k < D_/EMB_KS; k++)
        acc += tr[k] * Wp[(size_t)k * (2*D_)];
    embp[(size_t)ks * EMB_N + j] = acc;
}

__global__ void emb_red_kernel(const float* __restrict__ embp,
                               const float* __restrict__ b0,
                               const float* __restrict__ b1,
                               const float* __restrict__ b2,
                               float* __restrict__ emb) {
    int j = blockIdx.x * blockDim.x + threadIdx.x;
    int p  = j / (B_*2*D_);
    int r  = j - p * (B_*2*D_);
    int jj = r % (2*D_);
    const float* bb = (p == 0) ? b0 : (p == 1) ? b1 : b2;
    float acc = bb[jj];
    #pragma unroll
    for (int ks = 0; ks < EMB_KS; ks++)
        acc += embp[(size_t)ks * EMB_N + j];
    emb[j] = acc;
}

// ---------------------------------------------------------------------------
// AdaLN -> half. Warp-per-row.
// ---------------------------------------------------------------------------
__global__ void __launch_bounds__(256) adaln_kernel(const float* __restrict__ x,
                                                    const float* __restrict__ emb,
                                                    __half* __restrict__ out) {
    const int w = threadIdx.x >> 5, lane = threadIdx.x & 31;
    const int row = blockIdx.x * 8 + w;
    const int b   = row >> 11;
    const float* xr = x + (size_t)row * D_;

    float4 v[8];
    float s = 0.f, ss = 0.f;
    #pragma unroll
    for (int i = 0; i < 8; i++) {
        v[i] = *(const float4*)(xr + (i*32 + lane)*4);
        s  += v[i].x + v[i].y + v[i].z + v[i].w;
        ss += v[i].x*v[i].x + v[i].y*v[i].y + v[i].z*v[i].z + v[i].w*v[i].w;
    }
    #pragma unroll
    for (int off = 16; off; off >>= 1) {
        s  += __shfl_xor_sync(0xffffffffu, s,  off);
        ss += __shfl_xor_sync(0xffffffffu, ss, off);
    }
    float mean = s * (1.f/D_);
    float var  = ss * (1.f/D_) - mean*mean;
    float rstd = rsqrtf(var + 1e-5f);

    const float* eb = emb + b * (2*D_);
    __half* orow = out + (size_t)row * D_;
    #pragma unroll
    for (int i = 0; i < 8; i++) {
        int j = (i*32 + lane)*4;
        float4 sc = *(const float4*)(eb + j);
        float4 sh = *(const float4*)(eb + D_ + j);
        float a0 = (v[i].x - mean) * rstd * (1.f + sc.x) + sh.x;
        float a1 = (v[i].y - mean) * rstd * (1.f + sc.y) + sh.y;
        float a2 = (v[i].z - mean) * rstd * (1.f + sc.z) + sh.z;
        float a3 = (v[i].w - mean) * rstd * (1.f + sc.w) + sh.w;
        uint2 pk;
        pk.x = h2_u32(__floats2half2_rn(a0, a1));
        pk.y = h2_u32(__floats2half2_rn(a2, a3));
        *(uint2*)(orow + j) = pk;
    }
}

// ---------------------------------------------------------------------------
// fp16 mma GEMM, 3-stage cp.async pipeline, single barrier per iteration.
// ---------------------------------------------------------------------------
#define LDG2 40
#define GEMM_SMEM (3 * 2 * 128 * LDG2 * 2)

template<bool BIAS, bool RESID, bool OUTH, bool GLU>
__global__ void __launch_bounds__(256) gemm_h_kernel(
        const __half* __restrict__ A, const __half* __restrict__ Bt,
        const float* __restrict__ bias, const float* __restrict__ Rs,
        void* __restrict__ Cv, int M, int N, int K) {
    extern __shared__ __half sh[];

    const int tid  = threadIdx.x;
    const int wid  = tid >> 5, lane = tid & 31;
    const int grp  = lane >> 2, tig = lane & 3;
    const int wm   = (wid & 3) * 32;
    const int wn   = (wid >> 2) * 64;
    const int m0   = blockIdx.y * 128, n0 = blockIdx.x * 128;

    const uint32_t sm_u = smem_u32(sh);

    const int a_row = (lane & 15);
    const int a_col = (lane >> 4) << 3;
    const int b_row = ((lane >> 4) << 3) + (lane & 7);
    const int b_col = ((lane >> 3) & 1) << 3;

    float acc[2][8][4];
    #pragma unroll
    for (int i = 0; i < 2; i++)
        #pragma unroll
        for (int j = 0; j < 8; j++)
            #pragma unroll
            for (int q = 0; q < 4; q++) acc[i][j][q] = 0.f;

    const int niter = K >> 5;

    auto issue = [&](int it, int s) {
        const int k0 = it << 5;
        const uint32_t ab = sm_u + (uint32_t)(s*2*128*LDG2)*2;
        const uint32_t bb = ab + (uint32_t)(128*LDG2)*2;
        #pragma unroll
        for (int j = 0; j < 2; j++) {
            int idx = tid + j * 256;
            int r = idx >> 2, c8 = (idx & 3) << 3;
            cp16(ab + (uint32_t)(r*LDG2 + c8)*2, A  + (size_t)(m0 + r) * K + k0 + c8);
            cp16(bb + (uint32_t)(r*LDG2 + c8)*2, Bt + (size_t)(n0 + r) * K + k0 + c8);
        }
        CP_COMMIT();
    };

    issue(0, 0);
    if (niter > 1) issue(1, 1);

    int s = 0;
    for (int it = 0; it < niter; ++it) {
        if (it + 1 < niter) CP_WAIT1(); else CP_WAIT0();
        __syncthreads();   // data visibility + all warps done reading stage s (prev iter)
        if (it + 2 < niter) issue(it + 2, (s + 2) % 3);

        const uint32_t as_b = sm_u + (uint32_t)(s*2*128*LDG2)*2;
        const uint32_t bs_b = as_b + (uint32_t)(128*LDG2)*2;
        #pragma unroll
        for (int kk = 0; kk < 32; kk += 16) {
            uint32_t af[2][4], bf[8][2];
            #pragma unroll
            for (int mt = 0; mt < 2; mt++)
                ldmx4(af[mt], as_b + (uint32_t)((wm + mt*16 + a_row)*LDG2 + kk + a_col)*2);
            #pragma unroll
            for (int p = 0; p < 4; p++) {
                uint32_t r4[4];
                ldmx4(r4, bs_b + (uint32_t)((wn + p*16 + b_row)*LDG2 + kk + b_col)*2);
                bf[2*p  ][0] = r4[0]; bf[2*p  ][1] = r4[1];
                bf[2*p+1][0] = r4[2]; bf[2*p+1][1] = r4[3];
            }
            #pragma unroll
            for (int mt = 0; mt < 2; mt++)
                #pragma unroll
                for (int nt = 0; nt < 8; nt++)
                    mma_f16(acc[mt][nt], af[mt], bf[nt]);
        }
        s = (s + 1) % 3;
    }

    // Epilogue
    #pragma unroll
    for (int mt = 0; mt < 2; mt++) {
        #pragma unroll
        for (int nt = 0; nt < 8; nt++) {
            int row = m0 + wm + mt*16 + grp;
            int col = n0 + wn + nt*8 + tig*2;
            float2 v01 = make_float2(acc[mt][nt][0], acc[mt][nt][1]);
            float2 v23 = make_float2(acc[mt][nt][2], acc[mt][nt][3]);
            if (BIAS) {
                float2 bv = *(const float2*)(bias + col);
                v01.x += bv.x; v01.y += bv.y;
                v23.x += bv.x; v23.y += bv.y;
            }
            if (GLU) {
                __half* Gh = (__half*)Cv;
                int j = col >> 1;
                float g0 = v01.y, g1 = v23.y;
                float ge0 = 0.5f * g0 * (1.f + erff(g0 * 0.70710678118654752f));
                float ge1 = 0.5f * g1 * (1.f + erff(g1 * 0.70710678118654752f));
                Gh[(size_t)row * DFF_ + j]       = __float2half_rn(v01.x * ge0);
                Gh[(size_t)(row + 8) * DFF_ + j] = __float2half_rn(v23.x * ge1);
            } else {
                if (RESID) {
                    float2 r0 = *(const float2*)(Rs + (size_t)row * N + col);
                    float2 r1 = *(const float2*)(Rs + (size_t)(row + 8) * N + col);
                    v01.x += r0.x; v01.y += r0.y;
                    v23.x += r1.x; v23.y += r1.y;
                }
                if (OUTH) {
                    __half* Ch = (__half*)Cv;
                    *(__half2*)(Ch + (size_t)row * N + col) = __floats2half2_rn(v01.x, v01.y);
                    *(__half2*)(Ch + (size_t)(row + 8) * N + col) = __floats2half2_rn(v23.x, v23.y);
                } else {
                    float* Cf = (float*)Cv;
                    *(float2*)(Cf + (size_t)row * N + col) = v01;
                    *(float2*)(Cf + (size_t)(row + 8) * N + col) = v23;
                }
            }
        }
    }
}

// ---------------------------------------------------------------------------
// fp16 flash attention: 256 threads, 8 warps x 16 q-rows = 128 q-rows/CTA.
// 2 warps per SMSP -> softmax of one warp overlaps with HMMAs of the other.
// ---------------------------------------------------------------------------
#define LDF 72

__global__ void __launch_bounds__(256) flash_h_kernel(
        const __half* __restrict__ Q, int qstr,
        const __half* __restrict__ Kg, int kstr,
        const __half* __restrict__ Vg, int vstr,
        __half* __restrict__ O,
        int Sq, int Sk) {
    __shared__ __half Qs[128*LDF];
    __shared__ __half Ks[2][64*LDF];
    __shared__ __half Vs[2][64*LDF];

    const int tid = threadIdx.x;
    const int wid = tid >> 5, lane = tid & 31;
    const int grp = lane >> 2, tig = lane & 3;
    const int h = blockIdx.y, b = blockIdx.z;
    const int q0 = blockIdx.x * 128;
    const int wq = wid * 16;
    const int vrow = lane & 15;

    const uint32_t qs_u = smem_u32(Qs);
    const uint32_t ks_u = smem_u32(Ks);
    const uint32_t vs_u = smem_u32(Vs);

    const float qscale = 0.125f * 1.4426950408889634f;

    // Q: 128 rows x 64 cols = 1024 cp16 by 256 threads
    #pragma unroll
    for (int j = 0; j < 4; j++) {
        int i = tid + j * 256;
        int r = i >> 3, c8 = (i & 7) << 3;
        cp16(qs_u + (uint32_t)(r*LDF + c8)*2,
             Q + ((size_t)(b*Sq + q0 + r))*qstr + h*DH_ + c8);
    }
    auto issue_kv = [&](int kt, int s) {
        const int kbase = kt * 64;
        #pragma unroll
        for (int j = 0; j < 2; j++) {
            int i = tid + j * 256;
            int r = i >> 3, c8 = (i & 7) << 3;
            cp16(ks_u + (uint32_t)(s*64*LDF + r*LDF + c8)*2,
                 Kg + ((size_t)(b*Sk + kbase + r))*kstr + h*DH_ + c8);
            cp16(vs_u + (uint32_t)(s*64*LDF + r*LDF + c8)*2,
                 Vg + ((size_t)(b*Sk + kbase + r))*vstr + h*DH_ + c8);
        }
        CP_COMMIT();
    };
    issue_kv(0, 0);

    float o[8][4];
    #pragma unroll
    for (int nf = 0; nf < 8; nf++)
        #pragma unroll
        for (int q = 0; q < 4; q++) o[nf][q] = 0.f;
    float m0 = -1e30f, m1 = -1e30f, l0 = 0.f, l1 = 0.f;

    const int ntiles = Sk >> 6;
    for (int kt = 0; kt < ntiles; kt++) {
        const int s = kt & 1;
        CP_WAIT0();
        __syncthreads();
        if (kt + 1 < ntiles) issue_kv(kt + 1, s ^ 1);

        const __half* ks = Ks[s];
        float sc[8][4];
        #pragma unroll
        for (int nf = 0; nf < 8; nf++)
            #pragma unroll
            for (int q = 0; q < 4; q++) sc[nf][q] = 0.f;

        #pragma unroll
        for (int kk = 0; kk < 64; kk += 16) {
            uint32_t af[4];
            af[0] = *(const uint32_t*)&Qs[(wq + grp    )*LDF + kk + 2*tig    ];
            af[1] = *(const uint32_t*)&Qs[(wq + grp + 8)*LDF + kk + 2*tig    ];
            af[2] = *(const uint32_t*)&Qs[(wq + grp    )*LDF + kk + 2*tig + 8];
            af[3] = *(const uint32_t*)&Qs[(wq + grp + 8)*LDF + kk + 2*tig + 8];
            #pragma unroll
            for (int nf = 0; nf < 8; nf++) {
                uint32_t bf[2];
                bf[0] = *(const uint32_t*)&ks[(nf*8 + grp)*LDF + kk + 2*tig    ];
                bf[1] = *(const uint32_t*)&ks[(nf*8 + grp)*LDF + kk + 2*tig + 8];
                mma_f16(sc[nf], af, bf);
            }
        }

        float r0 = -1e30f, r1 = -1e30f;
        #pragma unroll
        for (int nf = 0; nf < 8; nf++) {
            r0 = fmaxf(r0, fmaxf(sc[nf][0], sc[nf][1]));
            r1 = fmaxf(r1, fmaxf(sc[nf][2], sc[nf][3]));
        }
        r0 = fmaxf(r0, __shfl_xor_sync(0xffffffffu, r0, 1));
        r0 = fmaxf(r0, __shfl_xor_sync(0xffffffffu, r0, 2));
        r1 = fmaxf(r1, __shfl_xor_sync(0xffffffffu, r1, 1));
        r1 = fmaxf(r1, __shfl_xor_sync(0xffffffffu, r1, 2));

        float mn0 = fmaxf(m0, r0 * qscale), mn1 = fmaxf(m1, r1 * qscale);
        float corr0 = ex2f(m0 - mn0), corr1 = ex2f(m1 - mn1);
        m0 = mn0; m1 = mn1;

        float rs0 = 0.f, rs1 = 0.f;
        uint32_t ph[8][2];
        #pragma unroll
        for (int nf = 0; nf < 8; nf++) {
            float p0 = ex2f(fmaf(sc[nf][0], qscale, -mn0));
            float p1 = ex2f(fmaf(sc[nf][1], qscale, -mn0));
            float p2 = ex2f(fmaf(sc[nf][2], qscale, -mn1));
            float p3 = ex2f(fmaf(sc[nf][3], qscale, -mn1));
            rs0 += p0 + p1; rs1 += p2 + p3;
            ph[nf][0] = h2_u32(__floats2half2_rn(p0, p1));
            ph[nf][1] = h2_u32(__floats2half2_rn(p2, p3));
        }
        rs0 += __shfl_xor_sync(0xffffffffu, rs0, 1);
        rs0 += __shfl_xor_sync(0xffffffffu, rs0, 2);
        rs1 += __shfl_xor_sync(0xffffffffu, rs1, 1);
        rs1 += __shfl_xor_sync(0xffffffffu, rs1, 2);
        l0 = l0 * corr0 + rs0;
        l1 = l1 * corr1 + rs1;

        #pragma unroll
        for (int nf = 0; nf < 8; nf++) {
            o[nf][0] *= corr0; o[nf][1] *= corr0;
            o[nf][2] *= corr1; o[nf][3] *= corr1;
        }

        const uint32_t vb = vs_u + (uint32_t)(s*64*LDF)*2;
        #pragma unroll
        for (int kk = 0; kk < 64; kk += 16) {
            const int nf2 = kk >> 3;
            uint32_t af[4] = { ph[nf2][0], ph[nf2][1], ph[nf2+1][0], ph[nf2+1][1] };
            #pragma unroll
            for (int nf = 0; nf < 8; nf++) {
                uint32_t b0, b1;
                ldmx2t(b0, b1, vb + (uint32_t)((kk + vrow)*LDF + nf*8)*2);
                uint32_t bf[2] = { b0, b1 };
                mma_f16(o[nf], af, bf);
            }
        }
    }

    float inv0 = 1.f / l0, inv1 = 1.f / l1;
    const size_t row0 = (size_t)(b*Sq + q0 + wq + grp);
    __half* op0 = O + row0 * INNER_ + h*DH_;
    __half* op1 = O + (row0 + 8) * INNER_ + h*DH_;
    #pragma unroll
    for (int nf = 0; nf < 8; nf++) {
        int col = nf*8 + 2*tig;
        *(__half2*)(op0 + col) = __floats2half2_rn(o[nf][0]*inv0, o[nf][1]*inv0);
        *(__half2*)(op1 + col) = __floats2half2_rn(o[nf][2]*inv1, o[nf][3]*inv1);
    }
}

// ---------------------------------------------------------------------------
// Launch
// ---------------------------------------------------------------------------
template<typename T>
static T* sym_addr_t(const void* s) {
    void* p = nullptr;
    cudaGetSymbolAddress(&p, s);
    return (T*)p;
}

extern "C" void kernel_launch(void* const* d_in, const int* in_sizes, int n_in,
                              void* d_out, int out_size) {
    const float* x_in   = (const float*)d_in[0];
    const float* t_in   = (const float*)d_in[1];
    const float* ctx_in = (const float*)d_in[2];
    const float* a1_wq = (const float*)d_in[3];
    const float* a1_wk = (const float*)d_in[4];
    const float* a1_wv = (const float*)d_in[5];
    const float* a1_wo = (const float*)d_in[6];
    const float* a1_bo = (const float*)d_in[7];
    const float* a2_wq = (const float*)d_in[8];
    const float* a2_wk = (const float*)d_in[9];
    const float* a2_wv = (const float*)d_in[10];
    const float* a2_wo = (const float*)d_in[11];
    const float* a2_bo = (const float*)d_in[12];
    const float* ff_w1 = (const float*)d_in[13];
    const float* ff_b1 = (const float*)d_in[14];
    const float* ff_w2 = (const float*)d_in[15];
    const float* ff_b2 = (const float*)d_in[16];
    const float* n1_w  = (const float*)d_in[17];
    const float* n1_b  = (const float*)d_in[18];
    const float* n2_w  = (const float*)d_in[19];
    const float* n2_b  = (const float*)d_in[20];
    const float* n3_w  = (const float*)d_in[21];
    const float* n3_b  = (const float*)d_in[22];
    float* out = (float*)d_out;

    float*  px    = sym_addr_t<float>(g_x);
    float*  pemb  = sym_addr_t<float>(g_emb);
    float*  pembp = sym_addr_t<float>(g_embp);
    float*  pb1i  = sym_addr_t<float>(g_b1i);
    __half* phh   = sym_addr_t<__half>(g_hh);
    __half* pqh   = sym_addr_t<__half>(g_qh);
    __half* pqkvh = sym_addr_t<__half>(g_qkvh);
    __half* pkvh  = sym_addr_t<__half>(g_kvh);
    __half* path  = sym_addr_t<__half>(g_atth);
    __half* pgluh = sym_addr_t<__half>(g_gluh);
    __half* pctxh = sym_addr_t<__half>(g_ctxh);

    __half* pqkv1T = sym_addr_t<__half>(g_qkv1T);
    __half* pa1woT = sym_addr_t<__half>(g_a1woT);
    __half* pa2wqT = sym_addr_t<__half>(g_a2wqT);
    __half* pkv2T  = sym_addr_t<__half>(g_kv2T);
    __half* pa2woT = sym_addr_t<__half>(g_a2woT);
    __half* pffw1T = sym_addr_t<__half>(g_ffw1T);
    __half* pffw2T = sym_addr_t<__half>(g_ffw2T);

    cudaFuncSetAttribute(gemm_h_kernel<false,false,true,false>,
                         cudaFuncAttributeMaxDynamicSharedMemorySize, GEMM_SMEM);
    cudaFuncSetAttribute(gemm_h_kernel<true,true,false,false>,
                         cudaFuncAttributeMaxDynamicSharedMemorySize, GEMM_SMEM);
    cudaFuncSetAttribute(gemm_h_kernel<true,false,true,true>,
                         cudaFuncAttributeMaxDynamicSharedMemorySize, GEMM_SMEM);

    static cudaStream_t s1 = nullptr;
    static cudaEvent_t evFork = nullptr, evPrep = nullptr, evKv = nullptr;
    if (!s1) {
        cudaStreamCreateWithFlags(&s1, cudaStreamNonBlocking);
        cudaEventCreateWithFlags(&evFork, cudaEventDisableTiming);
        cudaEventCreateWithFlags(&evPrep, cudaEventDisableTiming);
        cudaEventCreateWithFlags(&evKv,   cudaEventDisableTiming);
    }

    const int M  = B_ * S_;      // 4096
    const int Mc = B_ * CTX_;    // 512
    dim3 blk256(256);

    // ---- fork side stream ----
    cudaEventRecord(evFork, 0);
    cudaStreamWaitEvent(s1, evFork, 0);

    PrepParams P;
    int t0 = 0;
    auto addseg = [&](int i, const float* src, __half* dst, int R, int C, int glu) {
        P.seg[i] = {src, dst, R, C, glu, t0};
        t0 += (C >> 5) * (R >> 5);
    };
    addseg(0, a1_wq, pqkv1T,                      D_, INNER_, 0);
    addseg(1, a1_wk, pqkv1T + (size_t)INNER_*D_,  D_, INNER_, 0);
    addseg(2, a1_wv, pqkv1T + (size_t)2*INNER_*D_,D_, INNER_, 0);
    addseg(3, a1_wo, pa1woT, INNER_, D_, 0);
    addseg(4, a2_wq, pa2wqT, D_, INNER_, 0);
    addseg(5, a2_wk, pkv2T,  D_, INNER_, 0);
    addseg(6, a2_wv, pkv2T + (size_t)INNER_*D_, D_, INNER_, 0);
    addseg(7, a2_wo, pa2woT, INNER_, D_, 0);
    addseg(8, ff_w1, pffw1T, D_, 2*DFF_, 1);
    addseg(9, ff_w2, pffw2T, DFF_, D_, 0);
    P.total = t0;
    prep_kernel<<<t0, blk256, 0, s1>>>(P);
    cvt_h_kernel<<<(B_*CTX_*D_)/256, blk256, 0, s1>>>(ctx_in, pctxh);
    bias_ilv_kernel<<<DFF_/256, blk256, 0, s1>>>(ff_b1, pb1i);
    cudaEventRecord(evPrep, s1);
    dim3 gkv((2*INNER_)/128, Mc/128);
    gemm_h_kernel<false,false,true,false><<<gkv, blk256, GEMM_SMEM, s1>>>(
        pctxh, pkv2T, nullptr, nullptr, pkvh, Mc, 2*INNER_, D_);
    cudaEventRecord(evKv, s1);

    // main stream: embeddings + adaln1
    dim3 gemb(EMB_N/256, EMB_KS);
    emb_sk_kernel<<<gemb, blk256>>>(t_in, n1_w, n2_w, n3_w, pembp);
    emb_red_kernel<<<EMB_N/256, blk256>>>(pembp, n1_b, n2_b, n3_b, pemb);

    // ---------------- phase 1: AdaLN + self-attention ----------------
    adaln_kernel<<<M/8, blk256>>>(x_in, pemb, phh);

    cudaStreamWaitEvent(0, evPrep, 0);
    dim3 gqkv((3*INNER_)/128, M/128);
    gemm_h_kernel<false,false,true,false><<<gqkv, blk256, GEMM_SMEM>>>(phh, pqkv1T, nullptr, nullptr, pqkvh, M, 3*INNER_, D_);

    dim3 gf1(S_/128, H_, B_);
    flash_h_kernel<<<gf1, blk256>>>(pqkvh, 3*INNER_, pqkvh + INNER_, 3*INNER_,
                                    pqkvh + 2*INNER_, 3*INNER_, path, S_, S_);

    dim3 g2(D_/128, M/128);
    gemm_h_kernel<true,true,false,false><<<g2, blk256, GEMM_SMEM>>>(path, pa1woT, a1_bo, x_in, px, M, D_, INNER_);

    // ---------------- phase 2: AdaLN + cross-attention ----------------
    adaln_kernel<<<M/8, blk256>>>(px, pemb + B_*2*D_, phh);

    dim3 g1(INNER_/128, M/128);
    gemm_h_kernel<false,false,true,false><<<g1, blk256, GEMM_SMEM>>>(phh, pa2wqT, nullptr, nullptr, pqh, M, INNER_, D_);

    cudaStreamWaitEvent(0, evKv, 0);
    flash_h_kernel<<<gf1, blk256>>>(pqh, INNER_, pkvh, 2*INNER_,
                                    pkvh + INNER_, 2*INNER_, path, S_, CTX_);

    gemm_h_kernel<true,true,false,false><<<g2, blk256, GEMM_SMEM>>>(path, pa2woT, a2_bo, px, px, M, D_, INNER_);

    // ---------------- phase 3: AdaLN + fused GEGLU FFN ----------------
    adaln_kernel<<<M/8, blk256>>>(px, pemb + 2*B_*2*D_, phh);

    dim3 g3((2*DFF_)/128, M/128);
    gemm_h_kernel<true,false,true,true><<<g3, blk256, GEMM_SMEM>>>(phh, pffw1T, pb1i, nullptr, pgluh, M, 2*DFF_, D_);

    dim3 g4(D_/128, M/128);
    gemm_h_kernel<true,true,false,false><<<g4, blk256, GEMM_SMEM>>>(pgluh, pffw2T, ff_b2, px, out, M, D_, DFF_);
}

// round 12
// speedup vs baseline: 1.0744x; 1.0744x over previous
#include <cuda_runtime.h>
#include <cuda_fp16.h>
#include <math.h>
#include <cstdint>

// ---------------------------------------------------------------------------
// Problem constants
// ---------------------------------------------------------------------------
#define B_   2
#define S_   2048
#define CTX_ 256
#define D_   1024
#define H_   16
#define DH_  64
#define INNER_ 1024
#define DFF_ 4096
#define EMB_N   (3*B_*2*D_)    // 12288
#define EMB_KS  8

__device__ __forceinline__ uint32_t smem_u32(const void* p) {
    uint32_t a;
    asm("{ .reg .u64 t; cvta.to.shared.u64 t, %1; cvt.u32.u64 %0, t; }"
        : "=r"(a) : "l"(p));
    return a;
}
__device__ __forceinline__ void cp16(uint32_t dst, const void* src) {
    asm volatile("cp.async.cg.shared.global [%0], [%1], 16;" :: "r"(dst), "l"(src));
}
#define CP_COMMIT()  asm volatile("cp.async.commit_group;" ::: "memory")
#define CP_WAIT0()   asm volatile("cp.async.wait_group 0;" ::: "memory")
#define CP_WAIT1()   asm volatile("cp.async.wait_group 1;" ::: "memory")

__device__ __forceinline__ float ex2f(float x) {
    float y;
    asm("ex2.approx.f32 %0, %1;" : "=f"(y) : "f"(x));
    return y;
}
__device__ __forceinline__ uint32_t h2_u32(__half2 h) {
    union { __half2 h; uint32_t u; } c;
    c.h = h;
    return c.u;
}
__device__ __forceinline__ void mma_f16(float* c, const uint32_t* a, const uint32_t* b) {
    asm volatile(
        "mma.sync.aligned.m16n8k16.row.col.f32.f16.f16.f32 "
        "{%0,%1,%2,%3}, {%4,%5,%6,%7}, {%8,%9}, {%0,%1,%2,%3};"
        : "+f"(c[0]), "+f"(c[1]), "+f"(c[2]), "+f"(c[3])
        : "r"(a[0]), "r"(a[1]), "r"(a[2]), "r"(a[3]), "r"(b[0]), "r"(b[1]));
}
__device__ __forceinline__ void ldmx4(uint32_t* r, uint32_t addr) {
    asm volatile("ldmatrix.sync.aligned.m8n8.x4.shared.b16 {%0,%1,%2,%3}, [%4];"
        : "=r"(r[0]), "=r"(r[1]), "=r"(r[2]), "=r"(r[3]) : "r"(addr));
}
__device__ __forceinline__ void ldmx2t(uint32_t& b0, uint32_t& b1, uint32_t addr) {
    asm volatile("ldmatrix.sync.aligned.m8n8.x2.trans.shared.b16 {%0,%1}, [%2];"
        : "=r"(b0), "=r"(b1) : "r"(addr));
}

// ---------------------------------------------------------------------------
// Scratch (static device globals)
// ---------------------------------------------------------------------------
__device__ float  g_x   [B_*S_*D_];
__device__ float  g_emb [EMB_N];
__device__ float  g_embp[EMB_KS*EMB_N];
__device__ float  g_b1i [2*DFF_];
__device__ __half g_hh  [B_*S_*D_];
__device__ __half g_qh  [B_*S_*INNER_];
__device__ __half g_qkvh[B_*S_*3*INNER_];
__device__ __half g_kvh [B_*CTX_*2*INNER_];
__device__ __half g_atth[B_*S_*INNER_];
__device__ __half g_gluh[B_*S_*DFF_];
__device__ __half g_ctxh[B_*CTX_*D_];
__device__ __half g_qkv1T[3*INNER_*D_];
__device__ __half g_a1woT[D_*INNER_];
__device__ __half g_a2wqT[INNER_*D_];
__device__ __half g_kv2T [2*INNER_*D_];
__device__ __half g_a2woT[D_*INNER_];
__device__ __half g_ffw1T[2*DFF_*D_];     // GLU-interleaved rows
__device__ __half g_ffw2T[D_*DFF_];

// ---------------------------------------------------------------------------
// Merged weight prep
// ---------------------------------------------------------------------------
struct PrepSeg {
    const float* src;
    __half* dst;
    int R, C;
    int glu;
    int tile0;
};
struct PrepParams {
    PrepSeg seg[10];
    int total;
};

__global__ void __launch_bounds__(256) prep_kernel(PrepParams P) {
    __shared__ float t[32][33];
    int bid = blockIdx.x;
    int si = 0;
    #pragma unroll
    for (int i = 1; i < 10; i++)
        if (bid >= P.seg[i].tile0) si = i;
    const PrepSeg sg = P.seg[si];
    int local = bid - sg.tile0;
    int tilesX = sg.C >> 5;
    int bx = (local % tilesX) << 5;
    int by = (local / tilesX) << 5;

    int tx = threadIdx.x & 31, ty = threadIdx.x >> 5;
    int x = bx + tx;
    #pragma unroll
    for (int i = 0; i < 4; i++) {
        int y = by + ty + i * 8;
        t[ty + i*8][tx] = sg.src[(size_t)y * sg.C + x];
    }
    __syncthreads();
    int x2 = by + tx;
    #pragma unroll
    for (int i = 0; i < 4; i++) {
        int c = bx + ty + i * 8;
        int nr = c;
        if (sg.glu) nr = (c < DFF_) ? 2*c : 2*(c - DFF_) + 1;
        sg.dst[(size_t)nr * sg.R + x2] = __float2half_rn(t[tx][ty + i*8]);
    }
}

__global__ void cvt_h_kernel(const float* __restrict__ src, __half* __restrict__ dst) {
    int i = blockIdx.x * blockDim.x + threadIdx.x;
    dst[i] = __float2half_rn(src[i]);
}
__global__ void bias_ilv_kernel(const float* __restrict__ b, float* __restrict__ bi) {
    int j = blockIdx.x * blockDim.x + threadIdx.x;
    bi[2*j]   = b[j];
    bi[2*j+1] = b[DFF_ + j];
}

// ---------------------------------------------------------------------------
// Split-K AdaLN embedding
// ---------------------------------------------------------------------------
__global__ void emb_sk_kernel(const float* __restrict__ t,
                              const float* __restrict__ W0,
                              const float* __restrict__ W1,
                              const float* __restrict__ W2,
                              float* __restrict__ embp) {
    int j  = blockIdx.x * blockDim.x + threadIdx.x;
    int ks = blockIdx.y;
    int p  = j / (B_*2*D_);
    int r  = j - p * (B_*2*D_);
    int b  = r / (2*D_);
    int jj = r - b * (2*D_);
    const float* W = (p == 0) ? W0 : (p == 1) ? W1 : W2;
    const float* tr = t + b * D_ + ks * (D_/EMB_KS);
    const float* Wp = W + (size_t)(ks * (D_/EMB_KS)) * (2*D_) + jj;
    float acc = 0.f;
    #pragma unroll 8
    for (int k = 0; k < D_/EMB_KS; k++)
        acc += tr[k] * Wp[(size_t)k * (2*D_)];
    embp[(size_t)ks * EMB_N + j] = acc;
}

__global__ void emb_red_kernel(const float* __restrict__ embp,
                               const float* __restrict__ b0,
                               const float* __restrict__ b1,
                               const float* __restrict__ b2,
                               float* __restrict__ emb) {
    int j = blockIdx.x * blockDim.x + threadIdx.x;
    int p  = j / (B_*2*D_);
    int r  = j - p * (B_*2*D_);
    int jj = r % (2*D_);
    const float* bb = (p == 0) ? b0 : (p == 1) ? b1 : b2;
    float acc = bb[jj];
    #pragma unroll
    for (int ks = 0; ks < EMB_KS; ks++)
        acc += embp[(size_t)ks * EMB_N + j];
    emb[j] = acc;
}

// ---------------------------------------------------------------------------
// AdaLN -> half. Warp-per-row.
// ---------------------------------------------------------------------------
__global__ void __launch_bounds__(256) adaln_kernel(const float* __restrict__ x,
                                                    const float* __restrict__ emb,
                                                    __half* __restrict__ out) {
    const int w = threadIdx.x >> 5, lane = threadIdx.x & 31;
    const int row = blockIdx.x * 8 + w;
    const int b   = row >> 11;
    const float* xr = x + (size_t)row * D_;

    float4 v[8];
    float s = 0.f, ss = 0.f;
    #pragma unroll
    for (int i = 0; i < 8; i++) {
        v[i] = *(const float4*)(xr + (i*32 + lane)*4);
        s  += v[i].x + v[i].y + v[i].z + v[i].w;
        ss += v[i].x*v[i].x + v[i].y*v[i].y + v[i].z*v[i].z + v[i].w*v[i].w;
    }
    #pragma unroll
    for (int off = 16; off; off >>= 1) {
        s  += __shfl_xor_sync(0xffffffffu, s,  off);
        ss += __shfl_xor_sync(0xffffffffu, ss, off);
    }
    float mean = s * (1.f/D_);
    float var  = ss * (1.f/D_) - mean*mean;
    float rstd = rsqrtf(var + 1e-5f);

    const float* eb = emb + b * (2*D_);
    __half* orow = out + (size_t)row * D_;
    #pragma unroll
    for (int i = 0; i < 8; i++) {
        int j = (i*32 + lane)*4;
        float4 sc = *(const float4*)(eb + j);
        float4 sh = *(const float4*)(eb + D_ + j);
        float a0 = (v[i].x - mean) * rstd * (1.f + sc.x) + sh.x;
        float a1 = (v[i].y - mean) * rstd * (1.f + sc.y) + sh.y;
        float a2 = (v[i].z - mean) * rstd * (1.f + sc.z) + sh.z;
        float a3 = (v[i].w - mean) * rstd * (1.f + sc.w) + sh.w;
        uint2 pk;
        pk.x = h2_u32(__floats2half2_rn(a0, a1));
        pk.y = h2_u32(__floats2half2_rn(a2, a3));
        *(uint2*)(orow + j) = pk;
    }
}

// ---------------------------------------------------------------------------
// fp16 mma GEMM, 3-stage cp.async pipeline, single barrier per iteration.
// __launch_bounds__(256, 2): guarantee 2 CTAs/SM (reg cap 128).
// ---------------------------------------------------------------------------
#define LDG2 40
#define GEMM_SMEM (3 * 2 * 128 * LDG2 * 2)

template<bool BIAS, bool RESID, bool OUTH, bool GLU>
__global__ void __launch_bounds__(256, 2) gemm_h_kernel(
        const __half* __restrict__ A, const __half* __restrict__ Bt,
        const float* __restrict__ bias, const float* __restrict__ Rs,
        void* __restrict__ Cv, int M, int N, int K) {
    extern __shared__ __half sh[];

    const int tid  = threadIdx.x;
    const int wid  = tid >> 5, lane = tid & 31;
    const int grp  = lane >> 2, tig = lane & 3;
    const int wm   = (wid & 3) * 32;
    const int wn   = (wid >> 2) * 64;
    const int m0   = blockIdx.y * 128, n0 = blockIdx.x * 128;

    const uint32_t sm_u = smem_u32(sh);

    const int a_row = (lane & 15);
    const int a_col = (lane >> 4) << 3;
    const int b_row = ((lane >> 4) << 3) + (lane & 7);
    const int b_col = ((lane >> 3) & 1) << 3;

    float acc[2][8][4];
    #pragma unroll
    for (int i = 0; i < 2; i++)
        #pragma unroll
        for (int j = 0; j < 8; j++)
            #pragma unroll
            for (int q = 0; q < 4; q++) acc[i][j][q] = 0.f;

    const int niter = K >> 5;

    auto issue = [&](int it, int s) {
        const int k0 = it << 5;
        const uint32_t ab = sm_u + (uint32_t)(s*2*128*LDG2)*2;
        const uint32_t bb = ab + (uint32_t)(128*LDG2)*2;
        #pragma unroll
        for (int j = 0; j < 2; j++) {
            int idx = tid + j * 256;
            int r = idx >> 2, c8 = (idx & 3) << 3;
            cp16(ab + (uint32_t)(r*LDG2 + c8)*2, A  + (size_t)(m0 + r) * K + k0 + c8);
            cp16(bb + (uint32_t)(r*LDG2 + c8)*2, Bt + (size_t)(n0 + r) * K + k0 + c8);
        }
        CP_COMMIT();
    };

    issue(0, 0);
    if (niter > 1) issue(1, 1);

    int s = 0;
    for (int it = 0; it < niter; ++it) {
        if (it + 1 < niter) CP_WAIT1(); else CP_WAIT0();
        __syncthreads();   // data visibility + all warps done reading stage s (prev iter)
        if (it + 2 < niter) issue(it + 2, (s + 2) % 3);

        const uint32_t as_b = sm_u + (uint32_t)(s*2*128*LDG2)*2;
        const uint32_t bs_b = as_b + (uint32_t)(128*LDG2)*2;
        #pragma unroll
        for (int kk = 0; kk < 32; kk += 16) {
            uint32_t af[2][4], bf[8][2];
            #pragma unroll
            for (int mt = 0; mt < 2; mt++)
                ldmx4(af[mt], as_b + (uint32_t)((wm + mt*16 + a_row)*LDG2 + kk + a_col)*2);
            #pragma unroll
            for (int p = 0; p < 4; p++) {
                uint32_t r4[4];
                ldmx4(r4, bs_b + (uint32_t)((wn + p*16 + b_row)*LDG2 + kk + b_col)*2);
                bf[2*p  ][0] = r4[0]; bf[2*p  ][1] = r4[1];
                bf[2*p+1][0] = r4[2]; bf[2*p+1][1] = r4[3];
            }
            #pragma unroll
            for (int mt = 0; mt < 2; mt++)
                #pragma unroll
                for (int nt = 0; nt < 8; nt++)
                    mma_f16(acc[mt][nt], af[mt], bf[nt]);
        }
        s = (s + 1) % 3;
    }

    // Epilogue
    #pragma unroll
    for (int mt = 0; mt < 2; mt++) {
        #pragma unroll
        for (int nt = 0; nt < 8; nt++) {
            int row = m0 + wm + mt*16 + grp;
            int col = n0 + wn + nt*8 + tig*2;
            float2 v01 = make_float2(acc[mt][nt][0], acc[mt][nt][1]);
            float2 v23 = make_float2(acc[mt][nt][2], acc[mt][nt][3]);
            if (BIAS) {
                float2 bv = *(const float2*)(bias + col);
                v01.x += bv.x; v01.y += bv.y;
                v23.x += bv.x; v23.y += bv.y;
            }
            if (GLU) {
                __half* Gh = (__half*)Cv;
                int j = col >> 1;
                float g0 = v01.y, g1 = v23.y;
                float ge0 = 0.5f * g0 * (1.f + erff(g0 * 0.70710678118654752f));
                float ge1 = 0.5f * g1 * (1.f + erff(g1 * 0.70710678118654752f));
                Gh[(size_t)row * DFF_ + j]       = __float2half_rn(v01.x * ge0);
                Gh[(size_t)(row + 8) * DFF_ + j] = __float2half_rn(v23.x * ge1);
            } else {
                if (RESID) {
                    float2 r0 = *(const float2*)(Rs + (size_t)row * N + col);
                    float2 r1 = *(const float2*)(Rs + (size_t)(row + 8) * N + col);
                    v01.x += r0.x; v01.y += r0.y;
                    v23.x += r1.x; v23.y += r1.y;
                }
                if (OUTH) {
                    __half* Ch = (__half*)Cv;
                    *(__half2*)(Ch + (size_t)row * N + col) = __floats2half2_rn(v01.x, v01.y);
                    *(__half2*)(Ch + (size_t)(row + 8) * N + col) = __floats2half2_rn(v23.x, v23.y);
                } else {
                    float* Cf = (float*)Cv;
                    *(float2*)(Cf + (size_t)row * N + col) = v01;
                    *(float2*)(Cf + (size_t)(row + 8) * N + col) = v23;
                }
            }
        }
    }
}

// ---------------------------------------------------------------------------
// fp16 flash attention (R10 config): 128 threads, 4 warps x 16 q = 64 q/CTA.
// ---------------------------------------------------------------------------
#define LDF 72

__global__ void __launch_bounds__(128) flash_h_kernel(
        const __half* __restrict__ Q, int qstr,
        const __half* __restrict__ Kg, int kstr,
        const __half* __restrict__ Vg, int vstr,
        __half* __restrict__ O,
        int Sq, int Sk) {
    __shared__ __half Qs[64*LDF];
    __shared__ __half Ks[2][64*LDF];
    __shared__ __half Vs[2][64*LDF];

    const int tid = threadIdx.x;
    const int wid = tid >> 5, lane = tid & 31;
    const int grp = lane >> 2, tig = lane & 3;
    const int h = blockIdx.y, b = blockIdx.z;
    const int q0 = blockIdx.x * 64;
    const int wq = wid * 16;
    const int vrow = lane & 15;

    const uint32_t qs_u = smem_u32(Qs);
    const uint32_t ks_u = smem_u32(Ks);
    const uint32_t vs_u = smem_u32(Vs);

    const float qscale = 0.125f * 1.4426950408889634f;

    #pragma unroll
    for (int j = 0; j < 4; j++) {
        int i = tid + j * 128;
        int r = i >> 3, c8 = (i & 7) << 3;
        cp16(qs_u + (uint32_t)(r*LDF + c8)*2,
             Q + ((size_t)(b*Sq + q0 + r))*qstr + h*DH_ + c8);
    }
    auto issue_kv = [&](int kt, int s) {
        const int kbase = kt * 64;
        #pragma unroll
        for (int j = 0; j < 4; j++) {
            int i = tid + j * 128;
            int r = i >> 3, c8 = (i & 7) << 3;
            cp16(ks_u + (uint32_t)(s*64*LDF + r*LDF + c8)*2,
                 Kg + ((size_t)(b*Sk + kbase + r))*kstr + h*DH_ + c8);
            cp16(vs_u + (uint32_t)(s*64*LDF + r*LDF + c8)*2,
                 Vg + ((size_t)(b*Sk + kbase + r))*vstr + h*DH_ + c8);
        }
        CP_COMMIT();
    };
    issue_kv(0, 0);

    float o[8][4];
    #pragma unroll
    for (int nf = 0; nf < 8; nf++)
        #pragma unroll
        for (int q = 0; q < 4; q++) o[nf][q] = 0.f;
    float m0 = -1e30f, m1 = -1e30f, l0 = 0.f, l1 = 0.f;

    const int ntiles = Sk >> 6;
    for (int kt = 0; kt < ntiles; kt++) {
        const int s = kt & 1;
        CP_WAIT0();
        __syncthreads();
        if (kt + 1 < ntiles) issue_kv(kt + 1, s ^ 1);

        const __half* ks = Ks[s];
        float sc[8][4];
        #pragma unroll
        for (int nf = 0; nf < 8; nf++)
            #pragma unroll
            for (int q = 0; q < 4; q++) sc[nf][q] = 0.f;

        #pragma unroll
        for (int kk = 0; kk < 64; kk += 16) {
            uint32_t af[4];
            af[0] = *(const uint32_t*)&Qs[(wq + grp    )*LDF + kk + 2*tig    ];
            af[1] = *(const uint32_t*)&Qs[(wq + grp + 8)*LDF + kk + 2*tig    ];
            af[2] = *(const uint32_t*)&Qs[(wq + grp    )*LDF + kk + 2*tig + 8];
            af[3] = *(const uint32_t*)&Qs[(wq + grp + 8)*LDF + kk + 2*tig + 8];
            #pragma unroll
            for (int nf = 0; nf < 8; nf++) {
                uint32_t bf[2];
                bf[0] = *(const uint32_t*)&ks[(nf*8 + grp)*LDF + kk + 2*tig    ];
                bf[1] = *(const uint32_t*)&ks[(nf*8 + grp)*LDF + kk + 2*tig + 8];
                mma_f16(sc[nf], af, bf);
            }
        }

        float r0 = -1e30f, r1 = -1e30f;
        #pragma unroll
        for (int nf = 0; nf < 8; nf++) {
            r0 = fmaxf(r0, fmaxf(sc[nf][0], sc[nf][1]));
            r1 = fmaxf(r1, fmaxf(sc[nf][2], sc[nf][3]));
        }
        r0 = fmaxf(r0, __shfl_xor_sync(0xffffffffu, r0, 1));
        r0 = fmaxf(r0, __shfl_xor_sync(0xffffffffu, r0, 2));
        r1 = fmaxf(r1, __shfl_xor_sync(0xffffffffu, r1, 1));
        r1 = fmaxf(r1, __shfl_xor_sync(0xffffffffu, r1, 2));

        float mn0 = fmaxf(m0, r0 * qscale), mn1 = fmaxf(m1, r1 * qscale);
        float corr0 = ex2f(m0 - mn0), corr1 = ex2f(m1 - mn1);
        m0 = mn0; m1 = mn1;

        float rs0 = 0.f, rs1 = 0.f;
        uint32_t ph[8][2];
        #pragma unroll
        for (int nf = 0; nf < 8; nf++) {
            float p0 = ex2f(fmaf(sc[nf][0], qscale, -mn0));
            float p1 = ex2f(fmaf(sc[nf][1], qscale, -mn0));
            float p2 = ex2f(fmaf(sc[nf][2], qscale, -mn1));
            float p3 = ex2f(fmaf(sc[nf][3], qscale, -mn1));
            rs0 += p0 + p1; rs1 += p2 + p3;
            ph[nf][0] = h2_u32(__floats2half2_rn(p0, p1));
            ph[nf][1] = h2_u32(__floats2half2_rn(p2, p3));
        }
        rs0 += __shfl_xor_sync(0xffffffffu, rs0, 1);
        rs0 += __shfl_xor_sync(0xffffffffu, rs0, 2);
        rs1 += __shfl_xor_sync(0xffffffffu, rs1, 1);
        rs1 += __shfl_xor_sync(0xffffffffu, rs1, 2);
        l0 = l0 * corr0 + rs0;
        l1 = l1 * corr1 + rs1;

        #pragma unroll
        for (int nf = 0; nf < 8; nf++) {
            o[nf][0] *= corr0; o[nf][1] *= corr0;
            o[nf][2] *= corr1; o[nf][3] *= corr1;
        }

        const uint32_t vb = vs_u + (uint32_t)(s*64*LDF)*2;
        #pragma unroll
        for (int kk = 0; kk < 64; kk += 16) {
            const int nf2 = kk >> 3;
            uint32_t af[4] = { ph[nf2][0], ph[nf2][1], ph[nf2+1][0], ph[nf2+1][1] };
            #pragma unroll
            for (int nf = 0; nf < 8; nf++) {
                uint32_t b0, b1;
                ldmx2t(b0, b1, vb + (uint32_t)((kk + vrow)*LDF + nf*8)*2);
                uint32_t bf[2] = { b0, b1 };
                mma_f16(o[nf], af, bf);
            }
        }
    }

    float inv0 = 1.f / l0, inv1 = 1.f / l1;
    const size_t row0 = (size_t)(b*Sq + q0 + wq + grp);
    __half* op0 = O + row0 * INNER_ + h*DH_;
    __half* op1 = O + (row0 + 8) * INNER_ + h*DH_;
    #pragma unroll
    for (int nf = 0; nf < 8; nf++) {
        int col = nf*8 + 2*tig;
        *(__half2*)(op0 + col) = __floats2half2_rn(o[nf][0]*inv0, o[nf][1]*inv0);
        *(__half2*)(op1 + col) = __floats2half2_rn(o[nf][2]*inv1, o[nf][3]*inv1);
    }
}

// ---------------------------------------------------------------------------
// Launch
// ---------------------------------------------------------------------------
template<typename T>
static T* sym_addr_t(const void* s) {
    void* p = nullptr;
    cudaGetSymbolAddress(&p, s);
    return (T*)p;
}

extern "C" void kernel_launch(void* const* d_in, const int* in_sizes, int n_in,
                              void* d_out, int out_size) {
    const float* x_in   = (const float*)d_in[0];
    const float* t_in   = (const float*)d_in[1];
    const float* ctx_in = (const float*)d_in[2];
    const float* a1_wq = (const float*)d_in[3];
    const float* a1_wk = (const float*)d_in[4];
    const float* a1_wv = (const float*)d_in[5];
    const float* a1_wo = (const float*)d_in[6];
    const float* a1_bo = (const float*)d_in[7];
    const float* a2_wq = (const float*)d_in[8];
    const float* a2_wk = (const float*)d_in[9];
    const float* a2_wv = (const float*)d_in[10];
    const float* a2_wo = (const float*)d_in[11];
    const float* a2_bo = (const float*)d_in[12];
    const float* ff_w1 = (const float*)d_in[13];
    const float* ff_b1 = (const float*)d_in[14];
    const float* ff_w2 = (const float*)d_in[15];
    const float* ff_b2 = (const float*)d_in[16];
    const float* n1_w  = (const float*)d_in[17];
    const float* n1_b  = (const float*)d_in[18];
    const float* n2_w  = (const float*)d_in[19];
    const float* n2_b  = (const float*)d_in[20];
    const float* n3_w  = (const float*)d_in[21];
    const float* n3_b  = (const float*)d_in[22];
    float* out = (float*)d_out;

    float*  px    = sym_addr_t<float>(g_x);
    float*  pemb  = sym_addr_t<float>(g_emb);
    float*  pembp = sym_addr_t<float>(g_embp);
    float*  pb1i  = sym_addr_t<float>(g_b1i);
    __half* phh   = sym_addr_t<__half>(g_hh);
    __half* pqh   = sym_addr_t<__half>(g_qh);
    __half* pqkvh = sym_addr_t<__half>(g_qkvh);
    __half* pkvh  = sym_addr_t<__half>(g_kvh);
    __half* path  = sym_addr_t<__half>(g_atth);
    __half* pgluh = sym_addr_t<__half>(g_gluh);
    __half* pctxh = sym_addr_t<__half>(g_ctxh);

    __half* pqkv1T = sym_addr_t<__half>(g_qkv1T);
    __half* pa1woT = sym_addr_t<__half>(g_a1woT);
    __half* pa2wqT = sym_addr_t<__half>(g_a2wqT);
    __half* pkv2T  = sym_addr_t<__half>(g_kv2T);
    __half* pa2woT = sym_addr_t<__half>(g_a2woT);
    __half* pffw1T = sym_addr_t<__half>(g_ffw1T);
    __half* pffw2T = sym_addr_t<__half>(g_ffw2T);

    cudaFuncSetAttribute(gemm_h_kernel<false,false,true,false>,
                         cudaFuncAttributeMaxDynamicSharedMemorySize, GEMM_SMEM);
    cudaFuncSetAttribute(gemm_h_kernel<true,true,false,false>,
                         cudaFuncAttributeMaxDynamicSharedMemorySize, GEMM_SMEM);
    cudaFuncSetAttribute(gemm_h_kernel<true,false,true,true>,
                         cudaFuncAttributeMaxDynamicSharedMemorySize, GEMM_SMEM);

    static cudaStream_t s1 = nullptr;
    static cudaEvent_t evFork = nullptr, evPrep = nullptr, evKv = nullptr;
    if (!s1) {
        cudaStreamCreateWithFlags(&s1, cudaStreamNonBlocking);
        cudaEventCreateWithFlags(&evFork, cudaEventDisableTiming);
        cudaEventCreateWithFlags(&evPrep, cudaEventDisableTiming);
        cudaEventCreateWithFlags(&evKv,   cudaEventDisableTiming);
    }

    const int M  = B_ * S_;      // 4096
    const int Mc = B_ * CTX_;    // 512
    dim3 blk256(256);
    dim3 blk128(128);

    // ---- fork side stream ----
    cudaEventRecord(evFork, 0);
    cudaStreamWaitEvent(s1, evFork, 0);

    PrepParams P;
    int t0 = 0;
    auto addseg = [&](int i, const float* src, __half* dst, int R, int C, int glu) {
        P.seg[i] = {src, dst, R, C, glu, t0};
        t0 += (C >> 5) * (R >> 5);
    };
    addseg(0, a1_wq, pqkv1T,                      D_, INNER_, 0);
    addseg(1, a1_wk, pqkv1T + (size_t)INNER_*D_,  D_, INNER_, 0);
    addseg(2, a1_wv, pqkv1T + (size_t)2*INNER_*D_,D_, INNER_, 0);
    addseg(3, a1_wo, pa1woT, INNER_, D_, 0);
    addseg(4, a2_wq, pa2wqT, D_, INNER_, 0);
    addseg(5, a2_wk, pkv2T,  D_, INNER_, 0);
    addseg(6, a2_wv, pkv2T + (size_t)INNER_*D_, D_, INNER_, 0);
    addseg(7, a2_wo, pa2woT, INNER_, D_, 0);
    addseg(8, ff_w1, pffw1T, D_, 2*DFF_, 1);
    addseg(9, ff_w2, pffw2T, DFF_, D_, 0);
    P.total = t0;
    prep_kernel<<<t0, blk256, 0, s1>>>(P);
    cvt_h_kernel<<<(B_*CTX_*D_)/256, blk256, 0, s1>>>(ctx_in, pctxh);
    bias_ilv_kernel<<<DFF_/256, blk256, 0, s1>>>(ff_b1, pb1i);
    cudaEventRecord(evPrep, s1);
    dim3 gkv((2*INNER_)/128, Mc/128);
    gemm_h_kernel<false,false,true,false><<<gkv, blk256, GEMM_SMEM, s1>>>(
        pctxh, pkv2T, nullptr, nullptr, pkvh, Mc, 2*INNER_, D_);
    cudaEventRecord(evKv, s1);

    // main stream: embeddings + adaln1
    dim3 gemb(EMB_N/256, EMB_KS);
    emb_sk_kernel<<<gemb, blk256>>>(t_in, n1_w, n2_w, n3_w, pembp);
    emb_red_kernel<<<EMB_N/256, blk256>>>(pembp, n1_b, n2_b, n3_b, pemb);

    // ---------------- phase 1: AdaLN + self-attention ----------------
    adaln_kernel<<<M/8, blk256>>>(x_in, pemb, phh);

    cudaStreamWaitEvent(0, evPrep, 0);
    dim3 gqkv((3*INNER_)/128, M/128);
    gemm_h_kernel<false,false,true,false><<<gqkv, blk256, GEMM_SMEM>>>(phh, pqkv1T, nullptr, nullptr, pqkvh, M, 3*INNER_, D_);

    dim3 gf1(S_/64, H_, B_);
    flash_h_kernel<<<gf1, blk128>>>(pqkvh, 3*INNER_, pqkvh + INNER_, 3*INNER_,
                                    pqkvh + 2*INNER_, 3*INNER_, path, S_, S_);

    dim3 g2(D_/128, M/128);
    gemm_h_kernel<true,true,false,false><<<g2, blk256, GEMM_SMEM>>>(path, pa1woT, a1_bo, x_in, px, M, D_, INNER_);

    // ---------------- phase 2: AdaLN + cross-attention ----------------
    adaln_kernel<<<M/8, blk256>>>(px, pemb + B_*2*D_, phh);

    dim3 g1(INNER_/128, M/128);
    gemm_h_kernel<false,false,true,false><<<g1, blk256, GEMM_SMEM>>>(phh, pa2wqT, nullptr, nullptr, pqh, M, INNER_, D_);

    cudaStreamWaitEvent(0, evKv, 0);
    flash_h_kernel<<<gf1, blk128>>>(pqh, INNER_, pkvh, 2*INNER_,
                                    pkvh + INNER_, 2*INNER_, path, S_, CTX_);

    gemm_h_kernel<true,true,false,false><<<g2, blk256, GEMM_SMEM>>>(path, pa2woT, a2_bo, px, px, M, D_, INNER_);

    // ---------------- phase 3: AdaLN + fused GEGLU FFN ----------------
    adaln_kernel<<<M/8, blk256>>>(px, pemb + 2*B_*2*D_, phh);

    dim3 g3((2*DFF_)/128, M/128);
    gemm_h_kernel<true,false,true,true><<<g3, blk256, GEMM_SMEM>>>(phh, pffw1T, pb1i, nullptr, pgluh, M, 2*DFF_, D_);

    dim3 g4(D_/128, M/128);
    gemm_h_kernel<true,true,false,false><<<g4, blk256, GEMM_SMEM>>>(pgluh, pffw2T, ff_b2, px, out, M, D_, DFF_);
}

// round 13
// speedup vs baseline: 1.1615x; 1.0810x over previous
#include <cuda_runtime.h>
#include <cuda_fp16.h>
#include <math.h>
#include <cstdint>

// ---------------------------------------------------------------------------
// Problem constants
// ---------------------------------------------------------------------------
#define B_   2
#define S_   2048
#define CTX_ 256
#define D_   1024
#define H_   16
#define DH_  64
#define INNER_ 1024
#define DFF_ 4096
#define EMB_N   (3*B_*2*D_)    // 12288
#define EMB_KS  8

__device__ __forceinline__ uint32_t smem_u32(const void* p) {
    uint32_t a;
    asm("{ .reg .u64 t; cvta.to.shared.u64 t, %1; cvt.u32.u64 %0, t; }"
        : "=r"(a) : "l"(p));
    return a;
}
__device__ __forceinline__ void cp16(uint32_t dst, const void* src) {
    asm volatile("cp.async.cg.shared.global [%0], [%1], 16;" :: "r"(dst), "l"(src));
}
#define CP_COMMIT()  asm volatile("cp.async.commit_group;" ::: "memory")
#define CP_WAIT0()   asm volatile("cp.async.wait_group 0;" ::: "memory")
#define CP_WAIT1()   asm volatile("cp.async.wait_group 1;" ::: "memory")

__device__ __forceinline__ float ex2f(float x) {
    float y;
    asm("ex2.approx.f32 %0, %1;" : "=f"(y) : "f"(x));
    return y;
}
__device__ __forceinline__ uint32_t h2_u32(__half2 h) {
    union { __half2 h; uint32_t u; } c;
    c.h = h;
    return c.u;
}
__device__ __forceinline__ void mma_f16(float* c, const uint32_t* a, const uint32_t* b) {
    asm volatile(
        "mma.sync.aligned.m16n8k16.row.col.f32.f16.f16.f32 "
        "{%0,%1,%2,%3}, {%4,%5,%6,%7}, {%8,%9}, {%0,%1,%2,%3};"
        : "+f"(c[0]), "+f"(c[1]), "+f"(c[2]), "+f"(c[3])
        : "r"(a[0]), "r"(a[1]), "r"(a[2]), "r"(a[3]), "r"(b[0]), "r"(b[1]));
}
__device__ __forceinline__ void ldmx4(uint32_t* r, uint32_t addr) {
    asm volatile("ldmatrix.sync.aligned.m8n8.x4.shared.b16 {%0,%1,%2,%3}, [%4];"
        : "=r"(r[0]), "=r"(r[1]), "=r"(r[2]), "=r"(r[3]) : "r"(addr));
}
__device__ __forceinline__ void ldmx2t(uint32_t& b0, uint32_t& b1, uint32_t addr) {
    asm volatile("ldmatrix.sync.aligned.m8n8.x2.trans.shared.b16 {%0,%1}, [%2];"
        : "=r"(b0), "=r"(b1) : "r"(addr));
}

// ---------------------------------------------------------------------------
// Scratch (static device globals)
// ---------------------------------------------------------------------------
__device__ float  g_x   [B_*S_*D_];
__device__ float  g_emb [EMB_N];
__device__ float  g_embp[EMB_KS*EMB_N];
__device__ float  g_b1i [2*DFF_];
__device__ __half g_hh  [B_*S_*D_];
__device__ __half g_qh  [B_*S_*INNER_];
__device__ __half g_qkvh[B_*S_*3*INNER_];
__device__ __half g_kvh [B_*CTX_*2*INNER_];
__device__ __half g_atth[B_*S_*INNER_];
__device__ __half g_gluh[B_*S_*DFF_];
__device__ __half g_ctxh[B_*CTX_*D_];
__device__ __half g_qkv1T[3*INNER_*D_];
__device__ __half g_a1woT[D_*INNER_];
__device__ __half g_a2wqT[INNER_*D_];
__device__ __half g_kv2T [2*INNER_*D_];
__device__ __half g_a2woT[D_*INNER_];
__device__ __half g_ffw1T[2*DFF_*D_];     // GLU-interleaved rows
__device__ __half g_ffw2T[D_*DFF_];

// ---------------------------------------------------------------------------
// Merged weight prep
// ---------------------------------------------------------------------------
struct PrepSeg {
    const float* src;
    __half* dst;
    int R, C;
    int glu;
    int tile0;
};
struct PrepParams {
    PrepSeg seg[10];
    int total;
};

__global__ void __launch_bounds__(256) prep_kernel(PrepParams P) {
    __shared__ float t[32][33];
    int bid = blockIdx.x;
    int si = 0;
    #pragma unroll
    for (int i = 1; i < 10; i++)
        if (bid >= P.seg[i].tile0) si = i;
    const PrepSeg sg = P.seg[si];
    int local = bid - sg.tile0;
    int tilesX = sg.C >> 5;
    int bx = (local % tilesX) << 5;
    int by = (local / tilesX) << 5;

    int tx = threadIdx.x & 31, ty = threadIdx.x >> 5;
    int x = bx + tx;
    #pragma unroll
    for (int i = 0; i < 4; i++) {
        int y = by + ty + i * 8;
        t[ty + i*8][tx] = sg.src[(size_t)y * sg.C + x];
    }
    __syncthreads();
    int x2 = by + tx;
    #pragma unroll
    for (int i = 0; i < 4; i++) {
        int c = bx + ty + i * 8;
        int nr = c;
        if (sg.glu) nr = (c < DFF_) ? 2*c : 2*(c - DFF_) + 1;
        sg.dst[(size_t)nr * sg.R + x2] = __float2half_rn(t[tx][ty + i*8]);
    }
}

__global__ void cvt_h_kernel(const float* __restrict__ src, __half* __restrict__ dst) {
    int i = blockIdx.x * blockDim.x + threadIdx.x;
    dst[i] = __float2half_rn(src[i]);
}
__global__ void bias_ilv_kernel(const float* __restrict__ b, float* __restrict__ bi) {
    int j = blockIdx.x * blockDim.x + threadIdx.x;
    bi[2*j]   = b[j];
    bi[2*j+1] = b[DFF_ + j];
}

// ---------------------------------------------------------------------------
// Split-K AdaLN embedding
// ---------------------------------------------------------------------------
__global__ void emb_sk_kernel(const float* __restrict__ t,
                              const float* __restrict__ W0,
                              const float* __restrict__ W1,
                              const float* __restrict__ W2,
                              float* __restrict__ embp) {
    int j  = blockIdx.x * blockDim.x + threadIdx.x;
    int ks = blockIdx.y;
    int p  = j / (B_*2*D_);
    int r  = j - p * (B_*2*D_);
    int b  = r / (2*D_);
    int jj = r - b * (2*D_);
    const float* W = (p == 0) ? W0 : (p == 1) ? W1 : W2;
    const float* tr = t + b * D_ + ks * (D_/EMB_KS);
    const float* Wp = W + (size_t)(ks * (D_/EMB_KS)) * (2*D_) + jj;
    float acc = 0.f;
    #pragma unroll 8
    for (int k = 0; k < D_/EMB_KS; k++)
        acc += tr[k] * Wp[(size_t)k * (2*D_)];
    embp[(size_t)ks * EMB_N + j] = acc;
}

__global__ void emb_red_kernel(const float* __restrict__ embp,
                               const float* __restrict__ b0,
                               const float* __restrict__ b1,
                               const float* __restrict__ b2,
                               float* __restrict__ emb) {
    int j = blockIdx.x * blockDim.x + threadIdx.x;
    int p  = j / (B_*2*D_);
    int r  = j - p * (B_*2*D_);
    int jj = r % (2*D_);
    const float* bb = (p == 0) ? b0 : (p == 1) ? b1 : b2;
    float acc = bb[jj];
    #pragma unroll
    for (int ks = 0; ks < EMB_KS; ks++)
        acc += embp[(size_t)ks * EMB_N + j];
    emb[j] = acc;
}

// ---------------------------------------------------------------------------
// AdaLN -> half. Warp-per-row.
// ---------------------------------------------------------------------------
__global__ void __launch_bounds__(256) adaln_kernel(const float* __restrict__ x,
                                                    const float* __restrict__ emb,
                                                    __half* __restrict__ out) {
    const int w = threadIdx.x >> 5, lane = threadIdx.x & 31;
    const int row = blockIdx.x * 8 + w;
    const int b   = row >> 11;
    const float* xr = x + (size_t)row * D_;

    float4 v[8];
    float s = 0.f, ss = 0.f;
    #pragma unroll
    for (int i = 0; i < 8; i++) {
        v[i] = *(const float4*)(xr + (i*32 + lane)*4);
        s  += v[i].x + v[i].y + v[i].z + v[i].w;
        ss += v[i].x*v[i].x + v[i].y*v[i].y + v[i].z*v[i].z + v[i].w*v[i].w;
    }
    #pragma unroll
    for (int off = 16; off; off >>= 1) {
        s  += __shfl_xor_sync(0xffffffffu, s,  off);
        ss += __shfl_xor_sync(0xffffffffu, ss, off);
    }
    float mean = s * (1.f/D_);
    float var  = ss * (1.f/D_) - mean*mean;
    float rstd = rsqrtf(var + 1e-5f);

    const float* eb = emb + b * (2*D_);
    __half* orow = out + (size_t)row * D_;
    #pragma unroll
    for (int i = 0; i < 8; i++) {
        int j = (i*32 + lane)*4;
        float4 sc = *(const float4*)(eb + j);
        float4 sh = *(const float4*)(eb + D_ + j);
        float a0 = (v[i].x - mean) * rstd * (1.f + sc.x) + sh.x;
        float a1 = (v[i].y - mean) * rstd * (1.f + sc.y) + sh.y;
        float a2 = (v[i].z - mean) * rstd * (1.f + sc.z) + sh.z;
        float a3 = (v[i].w - mean) * rstd * (1.f + sc.w) + sh.w;
        uint2 pk;
        pk.x = h2_u32(__floats2half2_rn(a0, a1));
        pk.y = h2_u32(__floats2half2_rn(a2, a3));
        *(uint2*)(orow + j) = pk;
    }
}

// ---------------------------------------------------------------------------
// fp16 mma GEMM: K-chunk 64, 3-stage cp.async ring, single barrier/iter.
// Row stride 72 halves (36 words) -> conflict-free ldmatrix (same as flash).
// SMEM: 3 stages x (A+B) x 128 x 72 halves = 110.6 KB -> 2 CTAs/SM.
// ---------------------------------------------------------------------------
#define LDW 72
#define GEMM_SMEM (3 * 2 * 128 * LDW * 2)

template<bool BIAS, bool RESID, bool OUTH, bool GLU>
__global__ void __launch_bounds__(256, 2) gemm_h_kernel(
        const __half* __restrict__ A, const __half* __restrict__ Bt,
        const float* __restrict__ bias, const float* __restrict__ Rs,
        void* __restrict__ Cv, int M, int N, int K) {
    extern __shared__ __half sh[];

    const int tid  = threadIdx.x;
    const int wid  = tid >> 5, lane = tid & 31;
    const int grp  = lane >> 2, tig = lane & 3;
    const int wm   = (wid & 3) * 32;
    const int wn   = (wid >> 2) * 64;
    const int m0   = blockIdx.y * 128, n0 = blockIdx.x * 128;

    const uint32_t sm_u = smem_u32(sh);

    const int a_row = (lane & 15);
    const int a_col = (lane >> 4) << 3;
    const int b_row = ((lane >> 4) << 3) + (lane & 7);
    const int b_col = ((lane >> 3) & 1) << 3;

    float acc[2][8][4];
    #pragma unroll
    for (int i = 0; i < 2; i++)
        #pragma unroll
        for (int j = 0; j < 8; j++)
            #pragma unroll
            for (int q = 0; q < 4; q++) acc[i][j][q] = 0.f;

    const int niter = K >> 6;     // K-chunk 64

    auto issue = [&](int it, int s) {
        const int k0 = it << 6;
        const uint32_t ab = sm_u + (uint32_t)(s*2*128*LDW)*2;
        const uint32_t bb = ab + (uint32_t)(128*LDW)*2;
        #pragma unroll
        for (int j = 0; j < 4; j++) {
            int idx = tid + j * 256;
            int r = idx >> 3, c8 = (idx & 7) << 3;
            cp16(ab + (uint32_t)(r*LDW + c8)*2, A  + (size_t)(m0 + r) * K + k0 + c8);
            cp16(bb + (uint32_t)(r*LDW + c8)*2, Bt + (size_t)(n0 + r) * K + k0 + c8);
        }
        CP_COMMIT();
    };

    issue(0, 0);
    if (niter > 1) issue(1, 1);

    int s = 0;
    for (int it = 0; it < niter; ++it) {
        if (it + 1 < niter) CP_WAIT1(); else CP_WAIT0();
        __syncthreads();   // data visibility + all warps done reading stage s (prev iter)
        if (it + 2 < niter) issue(it + 2, (s + 2) % 3);

        const uint32_t as_b = sm_u + (uint32_t)(s*2*128*LDW)*2;
        const uint32_t bs_b = as_b + (uint32_t)(128*LDW)*2;
        #pragma unroll
        for (int kk = 0; kk < 64; kk += 16) {
            uint32_t af[2][4], bf[8][2];
            #pragma unroll
            for (int mt = 0; mt < 2; mt++)
                ldmx4(af[mt], as_b + (uint32_t)((wm + mt*16 + a_row)*LDW + kk + a_col)*2);
            #pragma unroll
            for (int p = 0; p < 4; p++) {
                uint32_t r4[4];
                ldmx4(r4, bs_b + (uint32_t)((wn + p*16 + b_row)*LDW + kk + b_col)*2);
                bf[2*p  ][0] = r4[0]; bf[2*p  ][1] = r4[1];
                bf[2*p+1][0] = r4[2]; bf[2*p+1][1] = r4[3];
            }
            #pragma unroll
            for (int mt = 0; mt < 2; mt++)
                #pragma unroll
                for (int nt = 0; nt < 8; nt++)
                    mma_f16(acc[mt][nt], af[mt], bf[nt]);
        }
        s = (s + 1) % 3;
    }

    // Epilogue
    #pragma unroll
    for (int mt = 0; mt < 2; mt++) {
        #pragma unroll
        for (int nt = 0; nt < 8; nt++) {
            int row = m0 + wm + mt*16 + grp;
            int col = n0 + wn + nt*8 + tig*2;
            float2 v01 = make_float2(acc[mt][nt][0], acc[mt][nt][1]);
            float2 v23 = make_float2(acc[mt][nt][2], acc[mt][nt][3]);
            if (BIAS) {
                float2 bv = *(const float2*)(bias + col);
                v01.x += bv.x; v01.y += bv.y;
                v23.x += bv.x; v23.y += bv.y;
            }
            if (GLU) {
                __half* Gh = (__half*)Cv;
                int j = col >> 1;
                float g0 = v01.y, g1 = v23.y;
                float ge0 = 0.5f * g0 * (1.f + erff(g0 * 0.70710678118654752f));
                float ge1 = 0.5f * g1 * (1.f + erff(g1 * 0.70710678118654752f));
                Gh[(size_t)row * DFF_ + j]       = __float2half_rn(v01.x * ge0);
                Gh[(size_t)(row + 8) * DFF_ + j] = __float2half_rn(v23.x * ge1);
            } else {
                if (RESID) {
                    float2 r0 = *(const float2*)(Rs + (size_t)row * N + col);
                    float2 r1 = *(const float2*)(Rs + (size_t)(row + 8) * N + col);
                    v01.x += r0.x; v01.y += r0.y;
                    v23.x += r1.x; v23.y += r1.y;
                }
                if (OUTH) {
                    __half* Ch = (__half*)Cv;
                    *(__half2*)(Ch + (size_t)row * N + col) = __floats2half2_rn(v01.x, v01.y);
                    *(__half2*)(Ch + (size_t)(row + 8) * N + col) = __floats2half2_rn(v23.x, v23.y);
                } else {
                    float* Cf = (float*)Cv;
                    *(float2*)(Cf + (size_t)row * N + col) = v01;
                    *(float2*)(Cf + (size_t)(row + 8) * N + col) = v23;
                }
            }
        }
    }
}

// ---------------------------------------------------------------------------
// fp16 flash attention (R10 config): 128 threads, 4 warps x 16 q = 64 q/CTA.
// ---------------------------------------------------------------------------
#define LDF 72

__global__ void __launch_bounds__(128) flash_h_kernel(
        const __half* __restrict__ Q, int qstr,
        const __half* __restrict__ Kg, int kstr,
        const __half* __restrict__ Vg, int vstr,
        __half* __restrict__ O,
        int Sq, int Sk) {
    __shared__ __half Qs[64*LDF];
    __shared__ __half Ks[2][64*LDF];
    __shared__ __half Vs[2][64*LDF];

    const int tid = threadIdx.x;
    const int wid = tid >> 5, lane = tid & 31;
    const int grp = lane >> 2, tig = lane & 3;
    const int h = blockIdx.y, b = blockIdx.z;
    const int q0 = blockIdx.x * 64;
    const int wq = wid * 16;
    const int vrow = lane & 15;

    const uint32_t qs_u = smem_u32(Qs);
    const uint32_t ks_u = smem_u32(Ks);
    const uint32_t vs_u = smem_u32(Vs);

    const float qscale = 0.125f * 1.4426950408889634f;

    #pragma unroll
    for (int j = 0; j < 4; j++) {
        int i = tid + j * 128;
        int r = i >> 3, c8 = (i & 7) << 3;
        cp16(qs_u + (uint32_t)(r*LDF + c8)*2,
             Q + ((size_t)(b*Sq + q0 + r))*qstr + h*DH_ + c8);
    }
    auto issue_kv = [&](int kt, int s) {
        const int kbase = kt * 64;
        #pragma unroll
        for (int j = 0; j < 4; j++) {
            int i = tid + j * 128;
            int r = i >> 3, c8 = (i & 7) << 3;
            cp16(ks_u + (uint32_t)(s*64*LDF + r*LDF + c8)*2,
                 Kg + ((size_t)(b*Sk + kbase + r))*kstr + h*DH_ + c8);
            cp16(vs_u + (uint32_t)(s*64*LDF + r*LDF + c8)*2,
                 Vg + ((size_t)(b*Sk + kbase + r))*vstr + h*DH_ + c8);
        }
        CP_COMMIT();
    };
    issue_kv(0, 0);

    float o[8][4];
    #pragma unroll
    for (int nf = 0; nf < 8; nf++)
        #pragma unroll
        for (int q = 0; q < 4; q++) o[nf][q] = 0.f;
    float m0 = -1e30f, m1 = -1e30f, l0 = 0.f, l1 = 0.f;

    const int ntiles = Sk >> 6;
    for (int kt = 0; kt < ntiles; kt++) {
        const int s = kt & 1;
        CP_WAIT0();
        __syncthreads();
        if (kt + 1 < ntiles) issue_kv(kt + 1, s ^ 1);

        const __half* ks = Ks[s];
        float sc[8][4];
        #pragma unroll
        for (int nf = 0; nf < 8; nf++)
            #pragma unroll
            for (int q = 0; q < 4; q++) sc[nf][q] = 0.f;

        #pragma unroll
        for (int kk = 0; kk < 64; kk += 16) {
            uint32_t af[4];
            af[0] = *(const uint32_t*)&Qs[(wq + grp    )*LDF + kk + 2*tig    ];
            af[1] = *(const uint32_t*)&Qs[(wq + grp + 8)*LDF + kk + 2*tig    ];
            af[2] = *(const uint32_t*)&Qs[(wq + grp    )*LDF + kk + 2*tig + 8];
            af[3] = *(const uint32_t*)&Qs[(wq + grp + 8)*LDF + kk + 2*tig + 8];
            #pragma unroll
            for (int nf = 0; nf < 8; nf++) {
                uint32_t bf[2];
                bf[0] = *(const uint32_t*)&ks[(nf*8 + grp)*LDF + kk + 2*tig    ];
                bf[1] = *(const uint32_t*)&ks[(nf*8 + grp)*LDF + kk + 2*tig + 8];
                mma_f16(sc[nf], af, bf);
            }
        }

        float r0 = -1e30f, r1 = -1e30f;
        #pragma unroll
        for (int nf = 0; nf < 8; nf++) {
            r0 = fmaxf(r0, fmaxf(sc[nf][0], sc[nf][1]));
            r1 = fmaxf(r1, fmaxf(sc[nf][2], sc[nf][3]));
        }
        r0 = fmaxf(r0, __shfl_xor_sync(0xffffffffu, r0, 1));
        r0 = fmaxf(r0, __shfl_xor_sync(0xffffffffu, r0, 2));
        r1 = fmaxf(r1, __shfl_xor_sync(0xffffffffu, r1, 1));
        r1 = fmaxf(r1, __shfl_xor_sync(0xffffffffu, r1, 2));

        float mn0 = fmaxf(m0, r0 * qscale), mn1 = fmaxf(m1, r1 * qscale);
        float corr0 = ex2f(m0 - mn0), corr1 = ex2f(m1 - mn1);
        m0 = mn0; m1 = mn1;

        float rs0 = 0.f, rs1 = 0.f;
        uint32_t ph[8][2];
        #pragma unroll
        for (int nf = 0; nf < 8; nf++) {
            float p0 = ex2f(fmaf(sc[nf][0], qscale, -mn0));
            float p1 = ex2f(fmaf(sc[nf][1], qscale, -mn0));
            float p2 = ex2f(fmaf(sc[nf][2], qscale, -mn1));
            float p3 = ex2f(fmaf(sc[nf][3], qscale, -mn1));
            rs0 += p0 + p1; rs1 += p2 + p3;
            ph[nf][0] = h2_u32(__floats2half2_rn(p0, p1));
            ph[nf][1] = h2_u32(__floats2half2_rn(p2, p3));
        }
        rs0 += __shfl_xor_sync(0xffffffffu, rs0, 1);
        rs0 += __shfl_xor_sync(0xffffffffu, rs0, 2);
        rs1 += __shfl_xor_sync(0xffffffffu, rs1, 1);
        rs1 += __shfl_xor_sync(0xffffffffu, rs1, 2);
        l0 = l0 * corr0 + rs0;
        l1 = l1 * corr1 + rs1;

        #pragma unroll
        for (int nf = 0; nf < 8; nf++) {
            o[nf][0] *= corr0; o[nf][1] *= corr0;
            o[nf][2] *= corr1; o[nf][3] *= corr1;
        }

        const uint32_t vb = vs_u + (uint32_t)(s*64*LDF)*2;
        #pragma unroll
        for (int kk = 0; kk < 64; kk += 16) {
            const int nf2 = kk >> 3;
            uint32_t af[4] = { ph[nf2][0], ph[nf2][1], ph[nf2+1][0], ph[nf2+1][1] };
            #pragma unroll
            for (int nf = 0; nf < 8; nf++) {
                uint32_t b0, b1;
                ldmx2t(b0, b1, vb + (uint32_t)((kk + vrow)*LDF + nf*8)*2);
                uint32_t bf[2] = { b0, b1 };
                mma_f16(o[nf], af, bf);
            }
        }
    }

    float inv0 = 1.f / l0, inv1 = 1.f / l1;
    const size_t row0 = (size_t)(b*Sq + q0 + wq + grp);
    __half* op0 = O + row0 * INNER_ + h*DH_;
    __half* op1 = O + (row0 + 8) * INNER_ + h*DH_;
    #pragma unroll
    for (int nf = 0; nf < 8; nf++) {
        int col = nf*8 + 2*tig;
        *(__half2*)(op0 + col) = __floats2half2_rn(o[nf][0]*inv0, o[nf][1]*inv0);
        *(__half2*)(op1 + col) = __floats2half2_rn(o[nf][2]*inv1, o[nf][3]*inv1);
    }
}

// ---------------------------------------------------------------------------
// Launch
// ---------------------------------------------------------------------------
template<typename T>
static T* sym_addr_t(const void* s) {
    void* p = nullptr;
    cudaGetSymbolAddress(&p, s);
    return (T*)p;
}

extern "C" void kernel_launch(void* const* d_in, const int* in_sizes, int n_in,
                              void* d_out, int out_size) {
    const float* x_in   = (const float*)d_in[0];
    const float* t_in   = (const float*)d_in[1];
    const float* ctx_in = (const float*)d_in[2];
    const float* a1_wq = (const float*)d_in[3];
    const float* a1_wk = (const float*)d_in[4];
    const float* a1_wv = (const float*)d_in[5];
    const float* a1_wo = (const float*)d_in[6];
    const float* a1_bo = (const float*)d_in[7];
    const float* a2_wq = (const float*)d_in[8];
    const float* a2_wk = (const float*)d_in[9];
    const float* a2_wv = (const float*)d_in[10];
    const float* a2_wo = (const float*)d_in[11];
    const float* a2_bo = (const float*)d_in[12];
    const float* ff_w1 = (const float*)d_in[13];
    const float* ff_b1 = (const float*)d_in[14];
    const float* ff_w2 = (const float*)d_in[15];
    const float* ff_b2 = (const float*)d_in[16];
    const float* n1_w  = (const float*)d_in[17];
    const float* n1_b  = (const float*)d_in[18];
    const float* n2_w  = (const float*)d_in[19];
    const float* n2_b  = (const float*)d_in[20];
    const float* n3_w  = (const float*)d_in[21];
    const float* n3_b  = (const float*)d_in[22];
    float* out = (float*)d_out;

    float*  px    = sym_addr_t<float>(g_x);
    float*  pemb  = sym_addr_t<float>(g_emb);
    float*  pembp = sym_addr_t<float>(g_embp);
    float*  pb1i  = sym_addr_t<float>(g_b1i);
    __half* phh   = sym_addr_t<__half>(g_hh);
    __half* pqh   = sym_addr_t<__half>(g_qh);
    __half* pqkvh = sym_addr_t<__half>(g_qkvh);
    __half* pkvh  = sym_addr_t<__half>(g_kvh);
    __half* path  = sym_addr_t<__half>(g_atth);
    __half* pgluh = sym_addr_t<__half>(g_gluh);
    __half* pctxh = sym_addr_t<__half>(g_ctxh);

    __half* pqkv1T = sym_addr_t<__half>(g_qkv1T);
    __half* pa1woT = sym_addr_t<__half>(g_a1woT);
    __half* pa2wqT = sym_addr_t<__half>(g_a2wqT);
    __half* pkv2T  = sym_addr_t<__half>(g_kv2T);
    __half* pa2woT = sym_addr_t<__half>(g_a2woT);
    __half* pffw1T = sym_addr_t<__half>(g_ffw1T);
    __half* pffw2T = sym_addr_t<__half>(g_ffw2T);

    cudaFuncSetAttribute(gemm_h_kernel<false,false,true,false>,
                         cudaFuncAttributeMaxDynamicSharedMemorySize, GEMM_SMEM);
    cudaFuncSetAttribute(gemm_h_kernel<true,true,false,false>,
                         cudaFuncAttributeMaxDynamicSharedMemorySize, GEMM_SMEM);
    cudaFuncSetAttribute(gemm_h_kernel<true,false,true,true>,
                         cudaFuncAttributeMaxDynamicSharedMemorySize, GEMM_SMEM);

    static cudaStream_t s1 = nullptr;
    static cudaEvent_t evFork = nullptr, evPrep = nullptr, evKv = nullptr;
    if (!s1) {
        cudaStreamCreateWithFlags(&s1, cudaStreamNonBlocking);
        cudaEventCreateWithFlags(&evFork, cudaEventDisableTiming);
        cudaEventCreateWithFlags(&evPrep, cudaEventDisableTiming);
        cudaEventCreateWithFlags(&evKv,   cudaEventDisableTiming);
    }

    const int M  = B_ * S_;      // 4096
    const int Mc = B_ * CTX_;    // 512
    dim3 blk256(256);
    dim3 blk128(128);

    // ---- fork side stream ----
    cudaEventRecord(evFork, 0);
    cudaStreamWaitEvent(s1, evFork, 0);

    PrepParams P;
    int t0 = 0;
    auto addseg = [&](int i, const float* src, __half* dst, int R, int C, int glu) {
        P.seg[i] = {src, dst, R, C, glu, t0};
        t0 += (C >> 5) * (R >> 5);
    };
    addseg(0, a1_wq, pqkv1T,                      D_, INNER_, 0);
    addseg(1, a1_wk, pqkv1T + (size_t)INNER_*D_,  D_, INNER_, 0);
    addseg(2, a1_wv, pqkv1T + (size_t)2*INNER_*D_,D_, INNER_, 0);
    addseg(3, a1_wo, pa1woT, INNER_, D_, 0);
    addseg(4, a2_wq, pa2wqT, D_, INNER_, 0);
    addseg(5, a2_wk, pkv2T,  D_, INNER_, 0);
    addseg(6, a2_wv, pkv2T + (size_t)INNER_*D_, D_, INNER_, 0);
    addseg(7, a2_wo, pa2woT, INNER_, D_, 0);
    addseg(8, ff_w1, pffw1T, D_, 2*DFF_, 1);
    addseg(9, ff_w2, pffw2T, DFF_, D_, 0);
    P.total = t0;
    prep_kernel<<<t0, blk256, 0, s1>>>(P);
    cvt_h_kernel<<<(B_*CTX_*D_)/256, blk256, 0, s1>>>(ctx_in, pctxh);
    bias_ilv_kernel<<<DFF_/256, blk256, 0, s1>>>(ff_b1, pb1i);
    cudaEventRecord(evPrep, s1);
    dim3 gkv((2*INNER_)/128, Mc/128);
    gemm_h_kernel<false,false,true,false><<<gkv, blk256, GEMM_SMEM, s1>>>(
        pctxh, pkv2T, nullptr, nullptr, pkvh, Mc, 2*INNER_, D_);
    cudaEventRecord(evKv, s1);

    // main stream: embeddings + adaln1
    dim3 gemb(EMB_N/256, EMB_KS);
    emb_sk_kernel<<<gemb, blk256>>>(t_in, n1_w, n2_w, n3_w, pembp);
    emb_red_kernel<<<EMB_N/256, blk256>>>(pembp, n1_b, n2_b, n3_b, pemb);

    // ---------------- phase 1: AdaLN + self-attention ----------------
    adaln_kernel<<<M/8, blk256>>>(x_in, pemb, phh);

    cudaStreamWaitEvent(0, evPrep, 0);
    dim3 gqkv((3*INNER_)/128, M/128);
    gemm_h_kernel<false,false,true,false><<<gqkv, blk256, GEMM_SMEM>>>(phh, pqkv1T, nullptr, nullptr, pqkvh, M, 3*INNER_, D_);

    dim3 gf1(S_/64, H_, B_);
    flash_h_kernel<<<gf1, blk128>>>(pqkvh, 3*INNER_, pqkvh + INNER_, 3*INNER_,
                                    pqkvh + 2*INNER_, 3*INNER_, path, S_, S_);

    dim3 g2(D_/128, M/128);
    gemm_h_kernel<true,true,false,false><<<g2, blk256, GEMM_SMEM>>>(path, pa1woT, a1_bo, x_in, px, M, D_, INNER_);

    // ---------------- phase 2: AdaLN + cross-attention ----------------
    adaln_kernel<<<M/8, blk256>>>(px, pemb + B_*2*D_, phh);

    dim3 g1(INNER_/128, M/128);
    gemm_h_kernel<false,false,true,false><<<g1, blk256, GEMM_SMEM>>>(phh, pa2wqT, nullptr, nullptr, pqh, M, INNER_, D_);

    cudaStreamWaitEvent(0, evKv, 0);
    flash_h_kernel<<<gf1, blk128>>>(pqh, INNER_, pkvh, 2*INNER_,
                                    pkvh + INNER_, 2*INNER_, path, S_, CTX_);

    gemm_h_kernel<true,true,false,false><<<g2, blk256, GEMM_SMEM>>>(path, pa2woT, a2_bo, px, px, M, D_, INNER_);

    // ---------------- phase 3: AdaLN + fused GEGLU FFN ----------------
    adaln_kernel<<<M/8, blk256>>>(px, pemb + 2*B_*2*D_, phh);

    dim3 g3((2*DFF_)/128, M/128);
    gemm_h_kernel<true,false,true,true><<<g3, blk256, GEMM_SMEM>>>(phh, pffw1T, pb1i, nullptr, pgluh, M, 2*DFF_, D_);

    dim3 g4(D_/128, M/128);
    gemm_h_kernel<true,true,false,false><<<g4, blk256, GEMM_SMEM>>>(pgluh, pffw2T, ff_b2, px, out, M, D_, DFF_);
}

// round 14
// speedup vs baseline: 1.2012x; 1.0342x over previous
#include <cuda_runtime.h>
#include <cuda_fp16.h>
#include <math.h>
#include <cstdint>

// ---------------------------------------------------------------------------
// Problem constants
// ---------------------------------------------------------------------------
#define B_   2
#define S_   2048
#define CTX_ 256
#define D_   1024
#define H_   16
#define DH_  64
#define INNER_ 1024
#define DFF_ 4096
#define EMB_N   (3*B_*2*D_)    // 12288
#define EMB_KS  8

__device__ __forceinline__ uint32_t smem_u32(const void* p) {
    uint32_t a;
    asm("{ .reg .u64 t; cvta.to.shared.u64 t, %1; cvt.u32.u64 %0, t; }"
        : "=r"(a) : "l"(p));
    return a;
}
__device__ __forceinline__ void cp16(uint32_t dst, const void* src) {
    asm volatile("cp.async.cg.shared.global [%0], [%1], 16;" :: "r"(dst), "l"(src));
}
#define CP_COMMIT()  asm volatile("cp.async.commit_group;" ::: "memory")
#define CP_WAIT0()   asm volatile("cp.async.wait_group 0;" ::: "memory")
#define CP_WAIT1()   asm volatile("cp.async.wait_group 1;" ::: "memory")

__device__ __forceinline__ float ex2f(float x) {
    float y;
    asm("ex2.approx.f32 %0, %1;" : "=f"(y) : "f"(x));
    return y;
}
__device__ __forceinline__ uint32_t h2_u32(__half2 h) {
    union { __half2 h; uint32_t u; } c;
    c.h = h;
    return c.u;
}
__device__ __forceinline__ void mma_f16(float* c, const uint32_t* a, const uint32_t* b) {
    asm volatile(
        "mma.sync.aligned.m16n8k16.row.col.f32.f16.f16.f32 "
        "{%0,%1,%2,%3}, {%4,%5,%6,%7}, {%8,%9}, {%0,%1,%2,%3};"
        : "+f"(c[0]), "+f"(c[1]), "+f"(c[2]), "+f"(c[3])
        : "r"(a[0]), "r"(a[1]), "r"(a[2]), "r"(a[3]), "r"(b[0]), "r"(b[1]));
}
__device__ __forceinline__ void ldmx4(uint32_t* r, uint32_t addr) {
    asm volatile("ldmatrix.sync.aligned.m8n8.x4.shared.b16 {%0,%1,%2,%3}, [%4];"
        : "=r"(r[0]), "=r"(r[1]), "=r"(r[2]), "=r"(r[3]) : "r"(addr));
}
__device__ __forceinline__ void ldmx2t(uint32_t& b0, uint32_t& b1, uint32_t addr) {
    asm volatile("ldmatrix.sync.aligned.m8n8.x2.trans.shared.b16 {%0,%1}, [%2];"
        : "=r"(b0), "=r"(b1) : "r"(addr));
}

// ---------------------------------------------------------------------------
// Scratch (static device globals)
// ---------------------------------------------------------------------------
__device__ float  g_x   [B_*S_*D_];
__device__ float  g_emb [EMB_N];
__device__ float  g_embp[EMB_KS*EMB_N];
__device__ float  g_b1i [2*DFF_];
__device__ __half g_hh  [B_*S_*D_];
__device__ __half g_qh  [B_*S_*INNER_];
__device__ __half g_qkvh[B_*S_*3*INNER_];
__device__ __half g_kvh [B_*CTX_*2*INNER_];
__device__ __half g_atth[B_*S_*INNER_];
__device__ __half g_gluh[B_*S_*DFF_];
__device__ __half g_ctxh[B_*CTX_*D_];
__device__ __half g_qkv1T[3*INNER_*D_];
__device__ __half g_a1woT[D_*INNER_];
__device__ __half g_a2wqT[INNER_*D_];
__device__ __half g_kv2T [2*INNER_*D_];
__device__ __half g_a2woT[D_*INNER_];
__device__ __half g_ffw1T[2*DFF_*D_];     // GLU-interleaved rows
__device__ __half g_ffw2T[D_*DFF_];

// ---------------------------------------------------------------------------
// Merged weight prep
// ---------------------------------------------------------------------------
struct PrepSeg {
    const float* src;
    __half* dst;
    int R, C;
    int glu;
    int tile0;
};
struct PrepParams {
    PrepSeg seg[10];
    int total;
};

__global__ void __launch_bounds__(256) prep_kernel(PrepParams P) {
    __shared__ float t[32][33];
    int bid = blockIdx.x;
    int si = 0;
    #pragma unroll
    for (int i = 1; i < 10; i++)
        if (bid >= P.seg[i].tile0) si = i;
    const PrepSeg sg = P.seg[si];
    int local = bid - sg.tile0;
    int tilesX = sg.C >> 5;
    int bx = (local % tilesX) << 5;
    int by = (local / tilesX) << 5;

    int tx = threadIdx.x & 31, ty = threadIdx.x >> 5;
    int x = bx + tx;
    #pragma unroll
    for (int i = 0; i < 4; i++) {
        int y = by + ty + i * 8;
        t[ty + i*8][tx] = sg.src[(size_t)y * sg.C + x];
    }
    __syncthreads();
    int x2 = by + tx;
    #pragma unroll
    for (int i = 0; i < 4; i++) {
        int c = bx + ty + i * 8;
        int nr = c;
        if (sg.glu) nr = (c < DFF_) ? 2*c : 2*(c - DFF_) + 1;
        sg.dst[(size_t)nr * sg.R + x2] = __float2half_rn(t[tx][ty + i*8]);
    }
}

__global__ void cvt_h_kernel(const float* __restrict__ src, __half* __restrict__ dst) {
    int i = blockIdx.x * blockDim.x + threadIdx.x;
    dst[i] = __float2half_rn(src[i]);
}
__global__ void bias_ilv_kernel(const float* __restrict__ b, float* __restrict__ bi) {
    int j = blockIdx.x * blockDim.x + threadIdx.x;
    bi[2*j]   = b[j];
    bi[2*j+1] = b[DFF_ + j];
}

// ---------------------------------------------------------------------------
// Split-K AdaLN embedding
// ---------------------------------------------------------------------------
__global__ void emb_sk_kernel(const float* __restrict__ t,
                              const float* __restrict__ W0,
                              const float* __restrict__ W1,
                              const float* __restrict__ W2,
                              float* __restrict__ embp) {
    int j  = blockIdx.x * blockDim.x + threadIdx.x;
    int ks = blockIdx.y;
    int p  = j / (B_*2*D_);
    int r  = j - p * (B_*2*D_);
    int b  = r / (2*D_);
    int jj = r - b * (2*D_);
    const float* W = (p == 0) ? W0 : (p == 1) ? W1 : W2;
    const float* tr = t + b * D_ + ks * (D_/EMB_KS);
    const float* Wp = W + (size_t)(ks * (D_/EMB_KS)) * (2*D_) + jj;
    float acc = 0.f;
    #pragma unroll 8
    for (int k = 0; k < D_/EMB_KS; k++)
        acc += tr[k] * Wp[(size_t)k * (2*D_)];
    embp[(size_t)ks * EMB_N + j] = acc;
}

__global__ void emb_red_kernel(const float* __restrict__ embp,
                               const float* __restrict__ b0,
                               const float* __restrict__ b1,
                               const float* __restrict__ b2,
                               float* __restrict__ emb) {
    int j = blockIdx.x * blockDim.x + threadIdx.x;
    int p  = j / (B_*2*D_);
    int r  = j - p * (B_*2*D_);
    int jj = r % (2*D_);
    const float* bb = (p == 0) ? b0 : (p == 1) ? b1 : b2;
    float acc = bb[jj];
    #pragma unroll
    for (int ks = 0; ks < EMB_KS; ks++)
        acc += embp[(size_t)ks * EMB_N + j];
    emb[j] = acc;
}

// ---------------------------------------------------------------------------
// AdaLN -> half. Warp-per-row.
// ---------------------------------------------------------------------------
__global__ void __launch_bounds__(256) adaln_kernel(const float* __restrict__ x,
                                                    const float* __restrict__ emb,
                                                    __half* __restrict__ out) {
    const int w = threadIdx.x >> 5, lane = threadIdx.x & 31;
    const int row = blockIdx.x * 8 + w;
    const int b   = row >> 11;
    const float* xr = x + (size_t)row * D_;

    float4 v[8];
    float s = 0.f, ss = 0.f;
    #pragma unroll
    for (int i = 0; i < 8; i++) {
        v[i] = *(const float4*)(xr + (i*32 + lane)*4);
        s  += v[i].x + v[i].y + v[i].z + v[i].w;
        ss += v[i].x*v[i].x + v[i].y*v[i].y + v[i].z*v[i].z + v[i].w*v[i].w;
    }
    #pragma unroll
    for (int off = 16; off; off >>= 1) {
        s  += __shfl_xor_sync(0xffffffffu, s,  off);
        ss += __shfl_xor_sync(0xffffffffu, ss, off);
    }
    float mean = s * (1.f/D_);
    float var  = ss * (1.f/D_) - mean*mean;
    float rstd = rsqrtf(var + 1e-5f);

    const float* eb = emb + b * (2*D_);
    __half* orow = out + (size_t)row * D_;
    #pragma unroll
    for (int i = 0; i < 8; i++) {
        int j = (i*32 + lane)*4;
        float4 sc = *(const float4*)(eb + j);
        float4 sh = *(const float4*)(eb + D_ + j);
        float a0 = (v[i].x - mean) * rstd * (1.f + sc.x) + sh.x;
        float a1 = (v[i].y - mean) * rstd * (1.f + sc.y) + sh.y;
        float a2 = (v[i].z - mean) * rstd * (1.f + sc.z) + sh.z;
        float a3 = (v[i].w - mean) * rstd * (1.f + sc.w) + sh.w;
        uint2 pk;
        pk.x = h2_u32(__floats2half2_rn(a0, a1));
        pk.y = h2_u32(__floats2half2_rn(a2, a3));
        *(uint2*)(orow + j) = pk;
    }
}

// ---------------------------------------------------------------------------
// fp16 mma GEMM: K-chunk 64, 3-stage cp.async ring, single barrier/iter,
// software-pipelined fragment double-buffer across k-slices.
// ---------------------------------------------------------------------------
#define LDW 72
#define GEMM_SMEM (3 * 2 * 128 * LDW * 2)

template<bool BIAS, bool RESID, bool OUTH, bool GLU>
__global__ void __launch_bounds__(256, 2) gemm_h_kernel(
        const __half* __restrict__ A, const __half* __restrict__ Bt,
        const float* __restrict__ bias, const float* __restrict__ Rs,
        void* __restrict__ Cv, int M, int N, int K) {
    extern __shared__ __half sh[];

    const int tid  = threadIdx.x;
    const int wid  = tid >> 5, lane = tid & 31;
    const int grp  = lane >> 2, tig = lane & 3;
    const int wm   = (wid & 3) * 32;
    const int wn   = (wid >> 2) * 64;
    const int m0   = blockIdx.y * 128, n0 = blockIdx.x * 128;

    const uint32_t sm_u = smem_u32(sh);

    const int a_row = (lane & 15);
    const int a_col = (lane >> 4) << 3;
    const int b_row = ((lane >> 4) << 3) + (lane & 7);
    const int b_col = ((lane >> 3) & 1) << 3;

    float acc[2][8][4];
    #pragma unroll
    for (int i = 0; i < 2; i++)
        #pragma unroll
        for (int j = 0; j < 8; j++)
            #pragma unroll
            for (int q = 0; q < 4; q++) acc[i][j][q] = 0.f;

    const int niter = K >> 6;     // K-chunk 64

    auto issue = [&](int it, int s) {
        const int k0 = it << 6;
        const uint32_t ab = sm_u + (uint32_t)(s*2*128*LDW)*2;
        const uint32_t bb = ab + (uint32_t)(128*LDW)*2;
        #pragma unroll
        for (int j = 0; j < 4; j++) {
            int idx = tid + j * 256;
            int r = idx >> 3, c8 = (idx & 7) << 3;
            cp16(ab + (uint32_t)(r*LDW + c8)*2, A  + (size_t)(m0 + r) * K + k0 + c8);
            cp16(bb + (uint32_t)(r*LDW + c8)*2, Bt + (size_t)(n0 + r) * K + k0 + c8);
        }
        CP_COMMIT();
    };

    // fragment loader for one k-slice (kk = slice*16)
    auto load_slice = [&](uint32_t af[2][4], uint32_t bf[8][2],
                          uint32_t as_b, uint32_t bs_b, int kk) {
        #pragma unroll
        for (int mt = 0; mt < 2; mt++)
            ldmx4(af[mt], as_b + (uint32_t)((wm + mt*16 + a_row)*LDW + kk + a_col)*2);
        #pragma unroll
        for (int p = 0; p < 4; p++) {
            uint32_t r4[4];
            ldmx4(r4, bs_b + (uint32_t)((wn + p*16 + b_row)*LDW + kk + b_col)*2);
            bf[2*p  ][0] = r4[0]; bf[2*p  ][1] = r4[1];
            bf[2*p+1][0] = r4[2]; bf[2*p+1][1] = r4[3];
        }
    };

    issue(0, 0);
    if (niter > 1) issue(1, 1);

    int s = 0;
    for (int it = 0; it < niter; ++it) {
        if (it + 1 < niter) CP_WAIT1(); else CP_WAIT0();
        __syncthreads();   // data visibility + all warps done reading stage s+2 (prev iter)

        const uint32_t as_b = sm_u + (uint32_t)(s*2*128*LDW)*2;
        const uint32_t bs_b = as_b + (uint32_t)(128*LDW)*2;

        uint32_t af[2][2][4], bf[2][8][2];
        // preload slice 0 fragments before anything else touches the LSU
        load_slice(af[0], bf[0], as_b, bs_b, 0);
        if (it + 2 < niter) issue(it + 2, (s + 2) % 3);

        #pragma unroll
        for (int sl = 0; sl < 4; sl++) {
            const int cur = sl & 1;
            if (sl < 3)
                load_slice(af[cur ^ 1], bf[cur ^ 1], as_b, bs_b, (sl + 1) * 16);
            #pragma unroll
            for (int mt = 0; mt < 2; mt++)
                #pragma unroll
                for (int nt = 0; nt < 8; nt++)
                    mma_f16(acc[mt][nt], af[cur][mt], bf[cur][nt]);
        }
        s = (s + 1) % 3;
    }

    // Epilogue
    #pragma unroll
    for (int mt = 0; mt < 2; mt++) {
        #pragma unroll
        for (int nt = 0; nt < 8; nt++) {
            int row = m0 + wm + mt*16 + grp;
            int col = n0 + wn + nt*8 + tig*2;
            float2 v01 = make_float2(acc[mt][nt][0], acc[mt][nt][1]);
            float2 v23 = make_float2(acc[mt][nt][2], acc[mt][nt][3]);
            if (BIAS) {
                float2 bv = *(const float2*)(bias + col);
                v01.x += bv.x; v01.y += bv.y;
                v23.x += bv.x; v23.y += bv.y;
            }
            if (GLU) {
                __half* Gh = (__half*)Cv;
                int j = col >> 1;
                float g0 = v01.y, g1 = v23.y;
                float ge0 = 0.5f * g0 * (1.f + erff(g0 * 0.70710678118654752f));
                float ge1 = 0.5f * g1 * (1.f + erff(g1 * 0.70710678118654752f));
                Gh[(size_t)row * DFF_ + j]       = __float2half_rn(v01.x * ge0);
                Gh[(size_t)(row + 8) * DFF_ + j] = __float2half_rn(v23.x * ge1);
            } else {
                if (RESID) {
                    float2 r0 = *(const float2*)(Rs + (size_t)row * N + col);
                    float2 r1 = *(const float2*)(Rs + (size_t)(row + 8) * N + col);
                    v01.x += r0.x; v01.y += r0.y;
                    v23.x += r1.x; v23.y += r1.y;
                }
                if (OUTH) {
                    __half* Ch = (__half*)Cv;
                    *(__half2*)(Ch + (size_t)row * N + col) = __floats2half2_rn(v01.x, v01.y);
                    *(__half2*)(Ch + (size_t)(row + 8) * N + col) = __floats2half2_rn(v23.x, v23.y);
                } else {
                    float* Cf = (float*)Cv;
                    *(float2*)(Cf + (size_t)row * N + col) = v01;
                    *(float2*)(Cf + (size_t)(row + 8) * N + col) = v23;
                }
            }
        }
    }
}

// ---------------------------------------------------------------------------
// fp16 flash attention (R10 config): 128 threads, 4 warps x 16 q = 64 q/CTA.
// ---------------------------------------------------------------------------
#define LDF 72

__global__ void __launch_bounds__(128) flash_h_kernel(
        const __half* __restrict__ Q, int qstr,
        const __half* __restrict__ Kg, int kstr,
        const __half* __restrict__ Vg, int vstr,
        __half* __restrict__ O,
        int Sq, int Sk) {
    __shared__ __half Qs[64*LDF];
    __shared__ __half Ks[2][64*LDF];
    __shared__ __half Vs[2][64*LDF];

    const int tid = threadIdx.x;
    const int wid = tid >> 5, lane = tid & 31;
    const int grp = lane >> 2, tig = lane & 3;
    const int h = blockIdx.y, b = blockIdx.z;
    const int q0 = blockIdx.x * 64;
    const int wq = wid * 16;
    const int vrow = lane & 15;

    const uint32_t qs_u = smem_u32(Qs);
    const uint32_t ks_u = smem_u32(Ks);
    const uint32_t vs_u = smem_u32(Vs);

    const float qscale = 0.125f * 1.4426950408889634f;

    #pragma unroll
    for (int j = 0; j < 4; j++) {
        int i = tid + j * 128;
        int r = i >> 3, c8 = (i & 7) << 3;
        cp16(qs_u + (uint32_t)(r*LDF + c8)*2,
             Q + ((size_t)(b*Sq + q0 + r))*qstr + h*DH_ + c8);
    }
    auto issue_kv = [&](int kt, int s) {
        const int kbase = kt * 64;
        #pragma unroll
        for (int j = 0; j < 4; j++) {
            int i = tid + j * 128;
            int r = i >> 3, c8 = (i & 7) << 3;
            cp16(ks_u + (uint32_t)(s*64*LDF + r*LDF + c8)*2,
                 Kg + ((size_t)(b*Sk + kbase + r))*kstr + h*DH_ + c8);
            cp16(vs_u + (uint32_t)(s*64*LDF + r*LDF + c8)*2,
                 Vg + ((size_t)(b*Sk + kbase + r))*vstr + h*DH_ + c8);
        }
        CP_COMMIT();
    };
    issue_kv(0, 0);

    float o[8][4];
    #pragma unroll
    for (int nf = 0; nf < 8; nf++)
        #pragma unroll
        for (int q = 0; q < 4; q++) o[nf][q] = 0.f;
    float m0 = -1e30f, m1 = -1e30f, l0 = 0.f, l1 = 0.f;

    const int ntiles = Sk >> 6;
    for (int kt = 0; kt < ntiles; kt++) {
        const int s = kt & 1;
        CP_WAIT0();
        __syncthreads();
        if (kt + 1 < ntiles) issue_kv(kt + 1, s ^ 1);

        const __half* ks = Ks[s];
        float sc[8][4];
        #pragma unroll
        for (int nf = 0; nf < 8; nf++)
            #pragma unroll
            for (int q = 0; q < 4; q++) sc[nf][q] = 0.f;

        #pragma unroll
        for (int kk = 0; kk < 64; kk += 16) {
            uint32_t af[4];
            af[0] = *(const uint32_t*)&Qs[(wq + grp    )*LDF + kk + 2*tig    ];
            af[1] = *(const uint32_t*)&Qs[(wq + grp + 8)*LDF + kk + 2*tig    ];
            af[2] = *(const uint32_t*)&Qs[(wq + grp    )*LDF + kk + 2*tig + 8];
            af[3] = *(const uint32_t*)&Qs[(wq + grp + 8)*LDF + kk + 2*tig + 8];
            #pragma unroll
            for (int nf = 0; nf < 8; nf++) {
                uint32_t bf[2];
                bf[0] = *(const uint32_t*)&ks[(nf*8 + grp)*LDF + kk + 2*tig    ];
                bf[1] = *(const uint32_t*)&ks[(nf*8 + grp)*LDF + kk + 2*tig + 8];
                mma_f16(sc[nf], af, bf);
            }
        }

        float r0 = -1e30f, r1 = -1e30f;
        #pragma unroll
        for (int nf = 0; nf < 8; nf++) {
            r0 = fmaxf(r0, fmaxf(sc[nf][0], sc[nf][1]));
            r1 = fmaxf(r1, fmaxf(sc[nf][2], sc[nf][3]));
        }
        r0 = fmaxf(r0, __shfl_xor_sync(0xffffffffu, r0, 1));
        r0 = fmaxf(r0, __shfl_xor_sync(0xffffffffu, r0, 2));
        r1 = fmaxf(r1, __shfl_xor_sync(0xffffffffu, r1, 1));
        r1 = fmaxf(r1, __shfl_xor_sync(0xffffffffu, r1, 2));

        float mn0 = fmaxf(m0, r0 * qscale), mn1 = fmaxf(m1, r1 * qscale);
        float corr0 = ex2f(m0 - mn0), corr1 = ex2f(m1 - mn1);
        m0 = mn0; m1 = mn1;

        float rs0 = 0.f, rs1 = 0.f;
        uint32_t ph[8][2];
        #pragma unroll
        for (int nf = 0; nf < 8; nf++) {
            float p0 = ex2f(fmaf(sc[nf][0], qscale, -mn0));
            float p1 = ex2f(fmaf(sc[nf][1], qscale, -mn0));
            float p2 = ex2f(fmaf(sc[nf][2], qscale, -mn1));
            float p3 = ex2f(fmaf(sc[nf][3], qscale, -mn1));
            rs0 += p0 + p1; rs1 += p2 + p3;
            ph[nf][0] = h2_u32(__floats2half2_rn(p0, p1));
            ph[nf][1] = h2_u32(__floats2half2_rn(p2, p3));
        }
        rs0 += __shfl_xor_sync(0xffffffffu, rs0, 1);
        rs0 += __shfl_xor_sync(0xffffffffu, rs0, 2);
        rs1 += __shfl_xor_sync(0xffffffffu, rs1, 1);
        rs1 += __shfl_xor_sync(0xffffffffu, rs1, 2);
        l0 = l0 * corr0 + rs0;
        l1 = l1 * corr1 + rs1;

        #pragma unroll
        for (int nf = 0; nf < 8; nf++) {
            o[nf][0] *= corr0; o[nf][1] *= corr0;
            o[nf][2] *= corr1; o[nf][3] *= corr1;
        }

        const uint32_t vb = vs_u + (uint32_t)(s*64*LDF)*2;
        #pragma unroll
        for (int kk = 0; kk < 64; kk += 16) {
            const int nf2 = kk >> 3;
            uint32_t af[4] = { ph[nf2][0], ph[nf2][1], ph[nf2+1][0], ph[nf2+1][1] };
            #pragma unroll
            for (int nf = 0; nf < 8; nf++) {
                uint32_t b0, b1;
                ldmx2t(b0, b1, vb + (uint32_t)((kk + vrow)*LDF + nf*8)*2);
                uint32_t bf[2] = { b0, b1 };
                mma_f16(o[nf], af, bf);
            }
        }
    }

    float inv0 = 1.f / l0, inv1 = 1.f / l1;
    const size_t row0 = (size_t)(b*Sq + q0 + wq + grp);
    __half* op0 = O + row0 * INNER_ + h*DH_;
    __half* op1 = O + (row0 + 8) * INNER_ + h*DH_;
    #pragma unroll
    for (int nf = 0; nf < 8; nf++) {
        int col = nf*8 + 2*tig;
        *(__half2*)(op0 + col) = __floats2half2_rn(o[nf][0]*inv0, o[nf][1]*inv0);
        *(__half2*)(op1 + col) = __floats2half2_rn(o[nf][2]*inv1, o[nf][3]*inv1);
    }
}

// ---------------------------------------------------------------------------
// Launch
// ---------------------------------------------------------------------------
template<typename T>
static T* sym_addr_t(const void* s) {
    void* p = nullptr;
    cudaGetSymbolAddress(&p, s);
    return (T*)p;
}

extern "C" void kernel_launch(void* const* d_in, const int* in_sizes, int n_in,
                              void* d_out, int out_size) {
    const float* x_in   = (const float*)d_in[0];
    const float* t_in   = (const float*)d_in[1];
    const float* ctx_in = (const float*)d_in[2];
    const float* a1_wq = (const float*)d_in[3];
    const float* a1_wk = (const float*)d_in[4];
    const float* a1_wv = (const float*)d_in[5];
    const float* a1_wo = (const float*)d_in[6];
    const float* a1_bo = (const float*)d_in[7];
    const float* a2_wq = (const float*)d_in[8];
    const float* a2_wk = (const float*)d_in[9];
    const float* a2_wv = (const float*)d_in[10];
    const float* a2_wo = (const float*)d_in[11];
    const float* a2_bo = (const float*)d_in[12];
    const float* ff_w1 = (const float*)d_in[13];
    const float* ff_b1 = (const float*)d_in[14];
    const float* ff_w2 = (const float*)d_in[15];
    const float* ff_b2 = (const float*)d_in[16];
    const float* n1_w  = (const float*)d_in[17];
    const float* n1_b  = (const float*)d_in[18];
    const float* n2_w  = (const float*)d_in[19];
    const float* n2_b  = (const float*)d_in[20];
    const float* n3_w  = (const float*)d_in[21];
    const float* n3_b  = (const float*)d_in[22];
    float* out = (float*)d_out;

    float*  px    = sym_addr_t<float>(g_x);
    float*  pemb  = sym_addr_t<float>(g_emb);
    float*  pembp = sym_addr_t<float>(g_embp);
    float*  pb1i  = sym_addr_t<float>(g_b1i);
    __half* phh   = sym_addr_t<__half>(g_hh);
    __half* pqh   = sym_addr_t<__half>(g_qh);
    __half* pqkvh = sym_addr_t<__half>(g_qkvh);
    __half* pkvh  = sym_addr_t<__half>(g_kvh);
    __half* path  = sym_addr_t<__half>(g_atth);
    __half* pgluh = sym_addr_t<__half>(g_gluh);
    __half* pctxh = sym_addr_t<__half>(g_ctxh);

    __half* pqkv1T = sym_addr_t<__half>(g_qkv1T);
    __half* pa1woT = sym_addr_t<__half>(g_a1woT);
    __half* pa2wqT = sym_addr_t<__half>(g_a2wqT);
    __half* pkv2T  = sym_addr_t<__half>(g_kv2T);
    __half* pa2woT = sym_addr_t<__half>(g_a2woT);
    __half* pffw1T = sym_addr_t<__half>(g_ffw1T);
    __half* pffw2T = sym_addr_t<__half>(g_ffw2T);

    cudaFuncSetAttribute(gemm_h_kernel<false,false,true,false>,
                         cudaFuncAttributeMaxDynamicSharedMemorySize, GEMM_SMEM);
    cudaFuncSetAttribute(gemm_h_kernel<true,true,false,false>,
                         cudaFuncAttributeMaxDynamicSharedMemorySize, GEMM_SMEM);
    cudaFuncSetAttribute(gemm_h_kernel<true,false,true,true>,
                         cudaFuncAttributeMaxDynamicSharedMemorySize, GEMM_SMEM);

    static cudaStream_t s1 = nullptr;
    static cudaEvent_t evFork = nullptr, evPrep = nullptr, evKv = nullptr;
    if (!s1) {
        cudaStreamCreateWithFlags(&s1, cudaStreamNonBlocking);
        cudaEventCreateWithFlags(&evFork, cudaEventDisableTiming);
        cudaEventCreateWithFlags(&evPrep, cudaEventDisableTiming);
        cudaEventCreateWithFlags(&evKv,   cudaEventDisableTiming);
    }

    const int M  = B_ * S_;      // 4096
    const int Mc = B_ * CTX_;    // 512
    dim3 blk256(256);
    dim3 blk128(128);

    // ---- fork side stream ----
    cudaEventRecord(evFork, 0);
    cudaStreamWaitEvent(s1, evFork, 0);

    PrepParams P;
    int t0 = 0;
    auto addseg = [&](int i, const float* src, __half* dst, int R, int C, int glu) {
        P.seg[i] = {src, dst, R, C, glu, t0};
        t0 += (C >> 5) * (R >> 5);
    };
    addseg(0, a1_wq, pqkv1T,                      D_, INNER_, 0);
    addseg(1, a1_wk, pqkv1T + (size_t)INNER_*D_,  D_, INNER_, 0);
    addseg(2, a1_wv, pqkv1T + (size_t)2*INNER_*D_,D_, INNER_, 0);
    addseg(3, a1_wo, pa1woT, INNER_, D_, 0);
    addseg(4, a2_wq, pa2wqT, D_, INNER_, 0);
    addseg(5, a2_wk, pkv2T,  D_, INNER_, 0);
    addseg(6, a2_wv, pkv2T + (size_t)INNER_*D_, D_, INNER_, 0);
    addseg(7, a2_wo, pa2woT, INNER_, D_, 0);
    addseg(8, ff_w1, pffw1T, D_, 2*DFF_, 1);
    addseg(9, ff_w2, pffw2T, DFF_, D_, 0);
    P.total = t0;
    prep_kernel<<<t0, blk256, 0, s1>>>(P);
    cvt_h_kernel<<<(B_*CTX_*D_)/256, blk256, 0, s1>>>(ctx_in, pctxh);
    bias_ilv_kernel<<<DFF_/256, blk256, 0, s1>>>(ff_b1, pb1i);
    cudaEventRecord(evPrep, s1);
    dim3 gkv((2*INNER_)/128, Mc/128);
    gemm_h_kernel<false,false,true,false><<<gkv, blk256, GEMM_SMEM, s1>>>(
        pctxh, pkv2T, nullptr, nullptr, pkvh, Mc, 2*INNER_, D_);
    cudaEventRecord(evKv, s1);

    // main stream: embeddings + adaln1
    dim3 gemb(EMB_N/256, EMB_KS);
    emb_sk_kernel<<<gemb, blk256>>>(t_in, n1_w, n2_w, n3_w, pembp);
    emb_red_kernel<<<EMB_N/256, blk256>>>(pembp, n1_b, n2_b, n3_b, pemb);

    // ---------------- phase 1: AdaLN + self-attention ----------------
    adaln_kernel<<<M/8, blk256>>>(x_in, pemb, phh);

    cudaStreamWaitEvent(0, evPrep, 0);
    dim3 gqkv((3*INNER_)/128, M/128);
    gemm_h_kernel<false,false,true,false><<<gqkv, blk256, GEMM_SMEM>>>(phh, pqkv1T, nullptr, nullptr, pqkvh, M, 3*INNER_, D_);

    dim3 gf1(S_/64, H_, B_);
    flash_h_kernel<<<gf1, blk128>>>(pqkvh, 3*INNER_, pqkvh + INNER_, 3*INNER_,
                                    pqkvh + 2*INNER_, 3*INNER_, path, S_, S_);

    dim3 g2(D_/128, M/128);
    gemm_h_kernel<true,true,false,false><<<g2, blk256, GEMM_SMEM>>>(path, pa1woT, a1_bo, x_in, px, M, D_, INNER_);

    // ---------------- phase 2: AdaLN + cross-attention ----------------
    adaln_kernel<<<M/8, blk256>>>(px, pemb + B_*2*D_, phh);

    dim3 g1(INNER_/128, M/128);
    gemm_h_kernel<false,false,true,false><<<g1, blk256, GEMM_SMEM>>>(phh, pa2wqT, nullptr, nullptr, pqh, M, INNER_, D_);

    cudaStreamWaitEvent(0, evKv, 0);
    flash_h_kernel<<<gf1, blk128>>>(pqh, INNER_, pkvh, 2*INNER_,
                                    pkvh + INNER_, 2*INNER_, path, S_, CTX_);

    gemm_h_kernel<true,true,false,false><<<g2, blk256, GEMM_SMEM>>>(path, pa2woT, a2_bo, px, px, M, D_, INNER_);

    // ---------------- phase 3: AdaLN + fused GEGLU FFN ----------------
    adaln_kernel<<<M/8, blk256>>>(px, pemb + 2*B_*2*D_, phh);

    dim3 g3((2*DFF_)/128, M/128);
    gemm_h_kernel<true,false,true,true><<<g3, blk256, GEMM_SMEM>>>(phh, pffw1T, pb1i, nullptr, pgluh, M, 2*DFF_, D_);

    dim3 g4(D_/128, M/128);
    gemm_h_kernel<true,true,false,false><<<g4, blk256, GEMM_SMEM>>>(pgluh, pffw2T, ff_b2, px, out, M, D_, DFF_);
}